// round 6
// baseline (speedup 1.0000x reference)
#include <cuda_runtime.h>
#include <cuda_bf16.h>
#include <cstdint>
#include <math.h>

// Problem constants (fixed shapes)
#define BB      4
#define NQ      900
#define DD      256
#define CH      256
#define HH      200
#define WW      200
#define HWSZ    40000
#define NHEADS  8
#define HDIM    32
#define NK      10
#define NPTS    4

// ---------------- scratch (device globals; no runtime allocation) ----------------
__device__ float g_q  [BB * NQ * DD];
__device__ float g_v  [BB * HWSZ * DD];          // projected BEV values (fp32)
__device__ float g_off[BB * NQ * NHEADS * NPTS * 2];
__device__ float g_aw [BB * NQ * NHEADS * NPTS];
__device__ float g_s  [BB * NQ * DD];
__device__ float g_t  [BB * NQ * DD];
__device__ __nv_bfloat16 g_bhi[DD * CH];         // WvT [n][k] hi
__device__ __nv_bfloat16 g_blo[DD * CH];         // WvT [n][k] lo

// ---------------- helpers ----------------
__device__ __forceinline__ uint32_t smem_u32(const void* p) {
    uint32_t a;
    asm("{ .reg .u64 t; cvta.to.shared.u64 t, %1; cvt.u32.u64 %0, t; }" : "=r"(a) : "l"(p));
    return a;
}
__device__ __forceinline__ uint32_t bf2u(__nv_bfloat16 a, __nv_bfloat16 b) {
    __nv_bfloat162 t(a, b);
    return *reinterpret_cast<uint32_t*>(&t);
}

#define LDSM_T(r, addr) \
    asm volatile("ldmatrix.sync.aligned.m8n8.x4.trans.shared.b16 {%0,%1,%2,%3}, [%4];" \
        : "=r"((r)[0]), "=r"((r)[1]), "=r"((r)[2]), "=r"((r)[3]) : "r"(addr))
#define LDSM(r, addr) \
    asm volatile("ldmatrix.sync.aligned.m8n8.x4.shared.b16 {%0,%1,%2,%3}, [%4];" \
        : "=r"((r)[0]), "=r"((r)[1]), "=r"((r)[2]), "=r"((r)[3]) : "r"(addr))
#define MMA_BF16(c, a, b0, b1) \
    asm volatile("mma.sync.aligned.m16n8k16.row.col.f32.bf16.bf16.f32 " \
        "{%0,%1,%2,%3},{%4,%5,%6,%7},{%8,%9},{%0,%1,%2,%3};" \
        : "+f"((c)[0]), "+f"((c)[1]), "+f"((c)[2]), "+f"((c)[3]) \
        : "r"((a)[0]), "r"((a)[1]), "r"((a)[2]), "r"((a)[3]), "r"(b0), "r"(b1))
#define CP16(dst, src) \
    asm volatile("cp.async.cg.shared.global [%0], [%1], 16;" :: "r"(dst), "l"(src))
#define CP_COMMIT()  asm volatile("cp.async.commit_group;" ::: "memory")
#define CP_WAIT0()   asm volatile("cp.async.wait_group 0;" ::: "memory")

__device__ __forceinline__ void split_store(char* dst_h, char* dst_l, uint32_t off, float4 v) {
    __nv_bfloat16 h0 = __float2bfloat16(v.x), h1 = __float2bfloat16(v.y);
    __nv_bfloat16 h2 = __float2bfloat16(v.z), h3 = __float2bfloat16(v.w);
    __nv_bfloat16 l0 = __float2bfloat16(v.x - __bfloat162float(h0));
    __nv_bfloat16 l1 = __float2bfloat16(v.y - __bfloat162float(h1));
    __nv_bfloat16 l2 = __float2bfloat16(v.z - __bfloat162float(h2));
    __nv_bfloat16 l3 = __float2bfloat16(v.w - __bfloat162float(h3));
    *(uint2*)(dst_h + off) = make_uint2(bf2u(h0, h1), bf2u(h2, h3));
    *(uint2*)(dst_l + off) = make_uint2(bf2u(l0, l1), bf2u(l2, l3));
}

// ---------------- Wv (K=256, N=256) -> WvT hi/lo [n][k] ----------------
__global__ __launch_bounds__(256) void conv_wv(const float* __restrict__ Wv)
{
    int idx = blockIdx.x * 256 + threadIdx.x;   // n*256 + k
    int n = idx >> 8, k = idx & 255;
    float v = Wv[k * DD + n];
    __nv_bfloat16 hi = __float2bfloat16(v);
    g_bhi[idx] = hi;
    g_blo[idx] = __float2bfloat16(v - __bfloat162float(hi));
}

// =====================================================================
// gemm_v: v[b,m,:] = bev^T[b,m,:] @ WvT^T + bv  (HMMA bf16 3-term split)
// CTA 64(m) x 256(n) FULL N. A resident in smem (converted once in
// prologue, XOR-swizzled [k 256][m 64]). B streamed via cp.async in 16
// chunks of k=16, double-buffered, XOR-swizzled [n 256][k 16].
// 8 warps = 2m x 4n (warp tile 32 x 64). Mainloop: cp.async+LDSM+MMA only.
// =====================================================================
// A: row k = 128B (64 m-els bf16); chunk16B c in row k stored at c^(k&7).
// B: row n = 32B (16 k-els); chunk16B c stored at c^((n>>2)&1).
#define VA(hl)        ((hl) * 32768)                       // 0, 32768
#define VB(buf, hl)   (65536 + ((buf) * 2 + (hl)) * 8192)  // ..98304
#define V_SMEM 98304

__global__ void __launch_bounds__(256, 2) gemm_v(
    const float* __restrict__ bev, const float* __restrict__ bias)
{
    extern __shared__ char smem[];
    const uint32_t sb = smem_u32(smem);
    const int tid = threadIdx.x;
    const int lane = tid & 31;
    const int wid = tid >> 5;
    const int warp_m = wid & 1;                  // 2 warps over m (32 each)
    const int warp_n = wid >> 1;                 // 4 warps over n (64 each)
    const int m0 = blockIdx.x * 64;
    const int b = blockIdx.y;

    const float* Ag = bev + (long)b * CH * HWSZ + m0;   // A[k][m], rows 256B

    // ---- B cp.async addressing (per thread, both buffers) ----
    // chunk id e = n*2 + c ; e = tid + p*256, p in 0..1 per hl
    uint32_t b_dst_off[2];                       // smem offset within a (buf,hl)
    const __nv_bfloat16* b_src[2][2];            // [p][hl] base (k0 added per chunk)
    {
#pragma unroll
        for (int p = 0; p < 2; p++) {
            int e = tid + p * 256;
            int n = e >> 1, c = e & 1;
            b_dst_off[p] = (uint32_t)(n * 32 + ((c ^ ((n >> 2) & 1)) << 4));
            b_src[p][0] = g_bhi + n * 256 + c * 8;
            b_src[p][1] = g_blo + n * 256 + c * 8;
        }
    }

    // ---- prologue: B chunk 0 in flight while A is converted ----
#pragma unroll
    for (int hl = 0; hl < 2; hl++)
#pragma unroll
        for (int p = 0; p < 2; p++)
            CP16(sb + VB(0, hl) + b_dst_off[p], (const void*)b_src[p][hl]);
    CP_COMMIT();

    // ---- A: load 64m x 256k fp32, split, store swizzled (once) ----
    {
#pragma unroll 4
        for (int p = 0; p < 16; p++) {
            int idx = tid + p * 256;             // float4 id 0..4095
            int k = idx >> 4;
            int m4 = (idx & 15) << 2;
            float4 v = *(const float4*)(Ag + (long)k * HWSZ + m4);
            int c = m4 >> 3;
            uint32_t off = (uint32_t)(k * 128 + ((c ^ (k & 7)) << 4) + ((m4 & 4) << 1));
            split_store(smem + VA(0), smem + VA(1), off, v);
        }
    }

    // ---- ldsm offsets ----
    const int tile = lane >> 3;
    const int kl = (lane & 7) + ((tile & 2) << 2);      // k row within 16 (swizzle-invariant)
    uint32_t aoff[2];                                    // per mf, A smem offset at kc=0
#pragma unroll
    for (int mf = 0; mf < 2; mf++) {
        int mchunk = (warp_m * 32 + mf * 16 + ((tile & 1) << 3)) >> 3;
        aoff[mf] = (uint32_t)(kl * 128 + (((mchunk ^ (kl & 7)) & 7) << 4));
    }
    uint32_t boff[4];                                    // per q, B smem offset in buffer
#pragma unroll
    for (int q = 0; q < 4; q++) {
        int n = warp_n * 64 + q * 16 + ((tile & 1) << 3) + (lane & 7);
        int c = (tile & 2) >> 1;
        boff[q] = (uint32_t)(n * 32 + ((c ^ ((n >> 2) & 1)) << 4));
    }

    float acc[2][8][4];
#pragma unroll
    for (int i = 0; i < 2; i++)
#pragma unroll
        for (int j = 0; j < 8; j++)
#pragma unroll
            for (int r = 0; r < 4; r++) acc[i][j][r] = 0.f;

    CP_WAIT0();
    __syncthreads();

    // ---- mainloop: 16 chunks of k=16 ----
#pragma unroll 2
    for (int kc = 0; kc < 16; kc++) {
        const int cur = kc & 1;
        if (kc < 15) {
            const int k0 = (kc + 1) * 16;
#pragma unroll
            for (int hl = 0; hl < 2; hl++)
#pragma unroll
                for (int p = 0; p < 2; p++)
                    CP16(sb + VB(1 - cur, hl) + b_dst_off[p],
                         (const void*)(b_src[p][hl] + k0));
            CP_COMMIT();
        }

        // A frags for this chunk (resident)
        uint32_t ah[2][4], al[2][4];
        const uint32_t akc = (uint32_t)(kc * 16 * 128);
#pragma unroll
        for (int mf = 0; mf < 2; mf++) {
            LDSM_T(ah[mf], sb + VA(0) + akc + aoff[mf]);
            LDSM_T(al[mf], sb + VA(1) + akc + aoff[mf]);
        }

        const uint32_t Bh = sb + VB(cur, 0), Bl = sb + VB(cur, 1);
#pragma unroll
        for (int q = 0; q < 4; q++) {
            uint32_t bh[4], bl[4];
            LDSM(bh, Bh + boff[q]);
            LDSM(bl, Bl + boff[q]);
#pragma unroll
            for (int h = 0; h < 2; h++) {
                const int nf = q * 2 + h;
#pragma unroll
                for (int mf = 0; mf < 2; mf++) {
                    MMA_BF16(acc[mf][nf], ah[mf], bh[h], bh[h + 2]);
                    MMA_BF16(acc[mf][nf], ah[mf], bl[h], bl[h + 2]);
                    MMA_BF16(acc[mf][nf], al[mf], bh[h], bh[h + 2]);
                }
            }
        }

        if (kc < 15) CP_WAIT0();
        __syncthreads();
    }

    // ---- epilogue: direct float2 stores ----
    float* vout = g_v + ((long)b * HWSZ + m0) * DD;
#pragma unroll
    for (int mf = 0; mf < 2; mf++) {
        int mrow = warp_m * 32 + mf * 16 + (lane >> 2);
#pragma unroll
        for (int nf = 0; nf < 8; nf++) {
            int n = warp_n * 64 + nf * 8 + (lane & 3) * 2;
            float2 bb = *(const float2*)(bias + n);
            *(float2*)(vout + (long)mrow * DD + n) =
                make_float2(acc[mf][nf][0] + bb.x, acc[mf][nf][1] + bb.y);
            *(float2*)(vout + (long)(mrow + 8) * DD + n) =
                make_float2(acc[mf][nf][2] + bb.x, acc[mf][nf][3] + bb.y);
        }
    }
}

// =====================================================================
// gemm_small: C[M x 256] = A[M x 256] @ W[256 x 256] + bias (+R)
// =====================================================================
#define S_APITCH 72
#define S_BPITCH 136
#define S_ASZ    (64 * S_APITCH * 2)            // 9216
#define S_BSZ    (64 * S_BPITCH * 2)            // 17408
#define S_AB(buf, hl) (((buf) * 2 + (hl)) * S_ASZ)               // 0..36864
#define S_BB(buf, hl) (36864 + ((buf) * 2 + (hl)) * S_BSZ)       // ..106496
#define S_SMEM 106496

template <bool RES>
__global__ void __launch_bounds__(256) gemm_small(
    const float* __restrict__ A, const float* __restrict__ Wm,
    const float* __restrict__ bias, const float* __restrict__ Rm,
    float* __restrict__ C, int M)
{
    extern __shared__ char smem[];
    const uint32_t sb = smem_u32(smem);
    const int tid = threadIdx.x;
    const int lane = tid & 31;
    const int wid = tid >> 5;
    const int warp_m = wid & 1;
    const int warp_n = wid >> 1;
    const int n0 = blockIdx.x * 128;
    const int m0 = blockIdx.y * 64;

    const int tile = lane >> 3;
    uint32_t aoff[2];
#pragma unroll
    for (int mf = 0; mf < 2; mf++) {
        int ml = warp_m * 32 + mf * 16 + ((tile & 1) << 3) + (lane & 7);
        int kcol = (tile & 2) << 2;
        aoff[mf] = (uint32_t)(ml * S_APITCH + kcol) * 2;
    }
    uint32_t boff[2];
#pragma unroll
    for (int q = 0; q < 2; q++) {
        int kr = (lane & 7) + ((tile & 2) << 2);
        int nc = warp_n * 32 + q * 16 + ((tile & 1) << 3);
        boff[q] = (uint32_t)(kr * S_BPITCH + nc) * 2;
    }

    float acc[2][4][4];
#pragma unroll
    for (int i = 0; i < 2; i++)
#pragma unroll
        for (int j = 0; j < 4; j++)
#pragma unroll
            for (int r = 0; r < 4; r++) acc[i][j][r] = 0.f;

    float4 rA[4], rB[8];

    auto g_load = [&](int kc) {
        const int k0 = kc * 64;
#pragma unroll
        for (int p = 0; p < 4; p++) {
            int idx = tid + p * 256;
            int m = idx >> 4, k4 = (idx & 15) << 2;
            rA[p] = (m0 + m < M) ? *(const float4*)(A + (long)(m0 + m) * DD + k0 + k4)
                                 : make_float4(0.f, 0.f, 0.f, 0.f);
        }
#pragma unroll
        for (int p = 0; p < 8; p++) {
            int idx = tid + p * 256;
            int k = idx >> 5, n4 = (idx & 31) << 2;
            rB[p] = *(const float4*)(Wm + (long)(k0 + k) * DD + n0 + n4);
        }
    };
    auto s_store = [&](int buf) {
#pragma unroll
        for (int p = 0; p < 4; p++) {
            int idx = tid + p * 256;
            int m = idx >> 4, k4 = (idx & 15) << 2;
            split_store(smem + S_AB(buf, 0), smem + S_AB(buf, 1),
                        (uint32_t)(m * S_APITCH + k4) * 2, rA[p]);
        }
#pragma unroll
        for (int p = 0; p < 8; p++) {
            int idx = tid + p * 256;
            int k = idx >> 5, n4 = (idx & 31) << 2;
            split_store(smem + S_BB(buf, 0), smem + S_BB(buf, 1),
                        (uint32_t)(k * S_BPITCH + n4) * 2, rB[p]);
        }
    };

    g_load(0);
    s_store(0);
    __syncthreads();

    for (int kc = 0; kc < 4; kc++) {
        const int cur = kc & 1;
        if (kc < 3) g_load(kc + 1);

        const uint32_t Ah = sb + S_AB(cur, 0), Al = sb + S_AB(cur, 1);
        const uint32_t Bh = sb + S_BB(cur, 0), Bl = sb + S_BB(cur, 1);
#pragma unroll
        for (int ks = 0; ks < 4; ks++) {
            uint32_t ah[2][4], al[2][4], bh[2][4], bl[2][4];
#pragma unroll
            for (int mf = 0; mf < 2; mf++) {
                LDSM(ah[mf], Ah + aoff[mf] + ks * 32);
                LDSM(al[mf], Al + aoff[mf] + ks * 32);
            }
#pragma unroll
            for (int q = 0; q < 2; q++) {
                LDSM_T(bh[q], Bh + boff[q] + ks * (16 * S_BPITCH * 2));
                LDSM_T(bl[q], Bl + boff[q] + ks * (16 * S_BPITCH * 2));
            }
#pragma unroll
            for (int mf = 0; mf < 2; mf++)
#pragma unroll
                for (int nf = 0; nf < 4; nf++) {
                    int q = nf >> 1, h = nf & 1;
                    MMA_BF16(acc[mf][nf], ah[mf], bh[q][h], bh[q][h + 2]);
                    MMA_BF16(acc[mf][nf], ah[mf], bl[q][h], bl[q][h + 2]);
                    MMA_BF16(acc[mf][nf], al[mf], bh[q][h], bh[q][h + 2]);
                }
        }
        if (kc < 3) s_store(1 - cur);
        __syncthreads();
    }

#pragma unroll
    for (int mf = 0; mf < 2; mf++) {
        int mrow = warp_m * 32 + mf * 16 + (lane >> 2);
#pragma unroll
        for (int nf = 0; nf < 4; nf++) {
            int n = warp_n * 32 + nf * 8 + (lane & 3) * 2;
            float2 bb = *(const float2*)(bias + n0 + n);
            float2 s0 = make_float2(acc[mf][nf][0] + bb.x, acc[mf][nf][1] + bb.y);
            float2 s1 = make_float2(acc[mf][nf][2] + bb.x, acc[mf][nf][3] + bb.y);
            if (RES) {
                if (m0 + mrow < M) {
                    float2 r = *(const float2*)(Rm + (long)(m0 + mrow) * DD + n0 + n);
                    s0.x += r.x; s0.y += r.y;
                }
                if (m0 + mrow + 8 < M) {
                    float2 r = *(const float2*)(Rm + (long)(m0 + mrow + 8) * DD + n0 + n);
                    s1.x += r.x; s1.y += r.y;
                }
            }
            if (m0 + mrow < M)
                *(float2*)(C + (long)(m0 + mrow) * DD + n0 + n) = s0;
            if (m0 + mrow + 8 < M)
                *(float2*)(C + (long)(m0 + mrow + 8) * DD + n0 + n) = s1;
        }
    }
}

// ---------------- offsets + attention weights ----------------
__global__ __launch_bounds__(128) void offattn_kernel(
    const float* __restrict__ Woff, const float* __restrict__ boff,
    const float* __restrict__ Wattn, const float* __restrict__ battn)
{
    __shared__ float qs[256];
    __shared__ float lg[32];
    const int row = blockIdx.x;
    const int tid = threadIdx.x;
    const float* qr = g_q + (long)row * DD;
    qs[tid] = qr[tid];
    qs[tid + 128] = qr[tid + 128];
    __syncthreads();

    if (tid < 64) {
        float s = boff[tid];
#pragma unroll 8
        for (int k = 0; k < 256; k++) s = fmaf(qs[k], Woff[k * 64 + tid], s);
        g_off[(long)row * 64 + tid] = s;
    } else if (tid < 96) {
        int j = tid - 64;
        float s = battn[j];
#pragma unroll 8
        for (int k = 0; k < 256; k++) s = fmaf(qs[k], Wattn[k * 32 + j], s);
        lg[j] = s;
    }
    __syncthreads();

    if (tid < 32) {
        float x = lg[tid];
        float m = x;
        m = fmaxf(m, __shfl_xor_sync(0xffffffffu, m, 1));
        m = fmaxf(m, __shfl_xor_sync(0xffffffffu, m, 2));
        float e = expf(x - m);
        float s = e;
        s += __shfl_xor_sync(0xffffffffu, s, 1);
        s += __shfl_xor_sync(0xffffffffu, s, 2);
        g_aw[(long)row * 32 + tid] = e / s;
    }
}

// ---------------- Bezier + bilinear sampling + weighted sum ----------------
__global__ __launch_bounds__(256) void sample_kernel(
    const float* __restrict__ ctrl, const float* __restrict__ pc)
{
    __shared__ float s_ctrl[8];
    __shared__ float s_off[64];
    __shared__ float s_aw[32];
    __shared__ int   s_idx[320][4];
    __shared__ float s_w[320][4];

    const int bn = blockIdx.x;
    const int b = bn / NQ;
    const int tid = threadIdx.x;

    if (tid < 8)  s_ctrl[tid] = ctrl[(long)bn * 8 + tid];
    else if (tid >= 32 && tid < 96) s_off[tid - 32] = g_off[(long)bn * 64 + (tid - 32)];
    else if (tid >= 96 && tid < 128) s_aw[tid - 96] = g_aw[(long)bn * 32 + (tid - 96)];
    __syncthreads();

    const float p0 = pc[0], p1 = pc[1];
    const float invx = 1.f / (pc[3] - p0);
    const float invy = 1.f / (pc[4] - p1);

    for (int it = tid; it < 320; it += 256) {
        const int h = it / 40;
        const int kp = it - h * 40;
        const int k = kp >> 2;
        const int p = kp & 3;

        float t = (float)k * (1.0f / (NK - 1));
        float u = 1.f - t;
        float b0 = u * u * u, b1 = 3.f * u * u * t, b2 = 3.f * u * t * t, b3 = t * t * t;
        float px = b0 * s_ctrl[0] + b1 * s_ctrl[2] + b2 * s_ctrl[4] + b3 * s_ctrl[6];
        float py = b0 * s_ctrl[1] + b1 * s_ctrl[3] + b2 * s_ctrl[5] + b3 * s_ctrl[7];
        float nx = fminf(fmaxf((px - p0) * invx, 0.01f), 0.99f);
        float ny = fminf(fmaxf((py - p1) * invy, 0.01f), 0.99f);

        float gx = (nx + s_off[h * 8 + p * 2 + 0] * (1.f / WW)) * WW - 0.5f;
        float gy = (ny + s_off[h * 8 + p * 2 + 1] * (1.f / HH)) * HH - 0.5f;
        float fx = floorf(gx), fy = floorf(gy);
        float wx = gx - fx, wy = gy - fy;
        int xi = (int)fx, yi = (int)fy;
        float ap = s_aw[h * 4 + p];

#pragma unroll
        for (int c = 0; c < 4; c++) {
            int dx = c & 1, dy = c >> 1;
            int ix = xi + dx, iy = yi + dy;
            bool valid = (ix >= 0) & (ix < WW) & (iy >= 0) & (iy < HH);
            float wgt = valid ? ap * (dx ? wx : 1.f - wx) * (dy ? wy : 1.f - wy) : 0.f;
            int cx = min(max(ix, 0), WW - 1);
            int cy = min(max(iy, 0), HH - 1);
            s_w[it][c] = wgt;
            s_idx[it][c] = cy * WW + cx;
        }
    }
    __syncthreads();

    const int h = tid >> 5, lane = tid & 31;
    const float* vb = g_v + (long)b * HWSZ * DD + h * HDIM + lane;
    float acc = 0.f;
    const int base = h * 40;
#pragma unroll 4
    for (int i = 0; i < 40; i++) {
#pragma unroll
        for (int c = 0; c < 4; c++) {
            float w = s_w[base + i][c];
            int idx = s_idx[base + i][c];
            acc = fmaf(w, vb[(long)idx * DD], acc);
        }
    }
    g_s[(long)bn * DD + h * HDIM + lane] = acc;
}

// ---------------- launch ----------------
extern "C" void kernel_launch(void* const* d_in, const int* in_sizes, int n_in,
                              void* d_out, int out_size)
{
    const float* query = (const float*)d_in[0];
    const float* ctrl  = (const float*)d_in[1];
    const float* bev   = (const float*)d_in[2];
    const float* pc    = (const float*)d_in[4];
    const float* Wq    = (const float*)d_in[5];
    const float* bq    = (const float*)d_in[6];
    const float* Wv    = (const float*)d_in[7];
    const float* bv    = (const float*)d_in[8];
    const float* Woff  = (const float*)d_in[9];
    const float* boff  = (const float*)d_in[10];
    const float* Wattn = (const float*)d_in[11];
    const float* battn = (const float*)d_in[12];
    const float* Wmo   = (const float*)d_in[13];
    const float* bmo   = (const float*)d_in[14];
    const float* Wo    = (const float*)d_in[15];
    const float* bo    = (const float*)d_in[16];
    float* out = (float*)d_out;

    float *pq, *ps, *pt;
    cudaGetSymbolAddress((void**)&pq, g_q);
    cudaGetSymbolAddress((void**)&ps, g_s);
    cudaGetSymbolAddress((void**)&pt, g_t);

    cudaFuncSetAttribute(gemm_v, cudaFuncAttributeMaxDynamicSharedMemorySize, V_SMEM);
    cudaFuncSetAttribute(gemm_small<false>, cudaFuncAttributeMaxDynamicSharedMemorySize, S_SMEM);
    cudaFuncSetAttribute(gemm_small<true>, cudaFuncAttributeMaxDynamicSharedMemorySize, S_SMEM);

    const int Mq = BB * NQ;                     // 3600
    const dim3 sg_grid(2, (Mq + 63) / 64);      // 2 x 57

    // q = query @ Wq + bq
    gemm_small<false><<<sg_grid, 256, S_SMEM>>>(query, Wq, bq, nullptr, pq, Mq);

    // offsets + attention weights
    offattn_kernel<<<Mq, 128>>>(Woff, boff, Wattn, battn);

    // Wv -> WvT hi/lo (bf16 split)
    conv_wv<<<DD, 256>>>(Wv);

    // v = bev^T @ Wv + bv
    gemm_v<<<dim3(HWSZ / 64, BB), 256, V_SMEM>>>(bev, bv);

    // bezier + bilinear sampling + attention-weighted sum
    sample_kernel<<<BB * NQ, 256>>>(ctrl, pc);

    // t = s @ Wmo + bmo + q
    gemm_small<true><<<sg_grid, 256, S_SMEM>>>(ps, Wmo, bmo, pq, pt, Mq);

    // out = t @ Wo + bo
    gemm_small<false><<<sg_grid, 256, S_SMEM>>>(pt, Wo, bo, nullptr, out, Mq);
}

// round 7
// speedup vs baseline: 1.2769x; 1.2769x over previous
#include <cuda_runtime.h>
#include <cuda_bf16.h>
#include <cuda_fp16.h>
#include <cstdint>
#include <math.h>

// Problem constants (fixed shapes)
#define BB      4
#define NQ      900
#define DD      256
#define CH      256
#define HH      200
#define WW      200
#define HWSZ    40000
#define NHEADS  8
#define HDIM    32
#define NK      10
#define NPTS    4

// ---------------- scratch (device globals; no runtime allocation) ----------------
__device__ float g_q  [BB * NQ * DD];
__device__ float g_v  [BB * HWSZ * DD];          // projected BEV values (fp32)
__device__ float g_off[BB * NQ * NHEADS * NPTS * 2];
__device__ float g_aw [BB * NQ * NHEADS * NPTS];
__device__ float g_s  [BB * NQ * DD];
__device__ float g_t  [BB * NQ * DD];
__device__ __half g_bhi[DD * CH];                // WvT [n][k] hi (fp16)
__device__ __half g_blo[DD * CH];                // WvT [n][k] lo (fp16)

// ---------------- helpers ----------------
__device__ __forceinline__ uint32_t smem_u32(const void* p) {
    uint32_t a;
    asm("{ .reg .u64 t; cvta.to.shared.u64 t, %1; cvt.u32.u64 %0, t; }" : "=r"(a) : "l"(p));
    return a;
}
__device__ __forceinline__ uint32_t bf2u(__nv_bfloat16 a, __nv_bfloat16 b) {
    __nv_bfloat162 t(a, b);
    return *reinterpret_cast<uint32_t*>(&t);
}
__device__ __forceinline__ uint32_t h2u(__half a, __half b) {
    __half2 t(a, b);
    return *reinterpret_cast<uint32_t*>(&t);
}

#define LDSM_T(r, addr) \
    asm volatile("ldmatrix.sync.aligned.m8n8.x4.trans.shared.b16 {%0,%1,%2,%3}, [%4];" \
        : "=r"((r)[0]), "=r"((r)[1]), "=r"((r)[2]), "=r"((r)[3]) : "r"(addr))
#define LDSM(r, addr) \
    asm volatile("ldmatrix.sync.aligned.m8n8.x4.shared.b16 {%0,%1,%2,%3}, [%4];" \
        : "=r"((r)[0]), "=r"((r)[1]), "=r"((r)[2]), "=r"((r)[3]) : "r"(addr))
#define MMA_BF16(c, a, b0, b1) \
    asm volatile("mma.sync.aligned.m16n8k16.row.col.f32.bf16.bf16.f32 " \
        "{%0,%1,%2,%3},{%4,%5,%6,%7},{%8,%9},{%0,%1,%2,%3};" \
        : "+f"((c)[0]), "+f"((c)[1]), "+f"((c)[2]), "+f"((c)[3]) \
        : "r"((a)[0]), "r"((a)[1]), "r"((a)[2]), "r"((a)[3]), "r"(b0), "r"(b1))
#define MMA_F16(c, a, b0, b1) \
    asm volatile("mma.sync.aligned.m16n8k16.row.col.f32.f16.f16.f32 " \
        "{%0,%1,%2,%3},{%4,%5,%6,%7},{%8,%9},{%0,%1,%2,%3};" \
        : "+f"((c)[0]), "+f"((c)[1]), "+f"((c)[2]), "+f"((c)[3]) \
        : "r"((a)[0]), "r"((a)[1]), "r"((a)[2]), "r"((a)[3]), "r"(b0), "r"(b1))
#define CP16(dst, src) \
    asm volatile("cp.async.cg.shared.global [%0], [%1], 16;" :: "r"(dst), "l"(src))
#define CP_COMMIT()  asm volatile("cp.async.commit_group;" ::: "memory")
#define CP_WAIT0()   asm volatile("cp.async.wait_group 0;" ::: "memory")

__device__ __forceinline__ void split_store(char* dst_h, char* dst_l, uint32_t off, float4 v) {
    __nv_bfloat16 h0 = __float2bfloat16(v.x), h1 = __float2bfloat16(v.y);
    __nv_bfloat16 h2 = __float2bfloat16(v.z), h3 = __float2bfloat16(v.w);
    __nv_bfloat16 l0 = __float2bfloat16(v.x - __bfloat162float(h0));
    __nv_bfloat16 l1 = __float2bfloat16(v.y - __bfloat162float(h1));
    __nv_bfloat16 l2 = __float2bfloat16(v.z - __bfloat162float(h2));
    __nv_bfloat16 l3 = __float2bfloat16(v.w - __bfloat162float(h3));
    *(uint2*)(dst_h + off) = make_uint2(bf2u(h0, h1), bf2u(h2, h3));
    *(uint2*)(dst_l + off) = make_uint2(bf2u(l0, l1), bf2u(l2, l3));
}

// ---------------- Wv (K=256, N=256) -> WvT hi/lo fp16 [n][k] ----------------
__global__ __launch_bounds__(256) void conv_wv(const float* __restrict__ Wv)
{
    int idx = blockIdx.x * 256 + threadIdx.x;   // n*256 + k
    int n = idx >> 8, k = idx & 255;
    float v = Wv[k * DD + n];
    __half hi = __float2half(v);
    g_bhi[idx] = hi;
    g_blo[idx] = __float2half(v - __half2float(hi));
}

// =====================================================================
// gemm_v: v[b,m,:] = bev^T[b,m,:] @ WvT^T + bv  (HMMA fp16, 2-term B-split)
// CTA 64(m) x 256(n) FULL N. A fp16 resident in smem (converted once in
// prologue, 32KB, XOR-swizzled [k 256][m 64]). B fp16 hi/lo streamed via
// cp.async in 8 chunks of k=32, double-buffered (64KB), XOR-swizzled.
// 8 warps = 2m x 4n (warp tile 32 x 64).
// v = A * (Bhi + Blo): 2 MMAs per frag pair, fp32 accum.
// =====================================================================
// A: row k = 128B (64 m-els fp16); 16B chunk c stored at c ^ (k&7).
// B: row n = 64B (32 k-els);       16B chunk c stored at c ^ ((n>>1)&3).
#define VA_OFF        0                                     // 32768 bytes
#define VB(buf, hl)   (32768 + ((buf) * 2 + (hl)) * 16384)  // ..98304
#define V_SMEM 98304

__global__ void __launch_bounds__(256, 2) gemm_v(
    const float* __restrict__ bev, const float* __restrict__ bias)
{
    extern __shared__ char smem[];
    const uint32_t sb = smem_u32(smem);
    const int tid = threadIdx.x;
    const int lane = tid & 31;
    const int wid = tid >> 5;
    const int warp_m = wid & 1;                  // 2 warps over m (32 each)
    const int warp_n = wid >> 1;                 // 4 warps over n (64 each)
    const int m0 = blockIdx.x * 64;
    const int b = blockIdx.y;

    const float* Ag = bev + (long)b * CH * HWSZ + m0;   // A[k][m], fp32 rows

    // ---- B cp.async addressing: chunk e = n*4 + c (4 chunks of 16B per row) ----
    uint32_t b_dst_off[4];
    const __half* b_src_h[4];
    const __half* b_src_l[4];
#pragma unroll
    for (int p = 0; p < 4; p++) {
        int e = tid + p * 256;                   // 0..1023
        int n = e >> 2, c = e & 3;
        b_dst_off[p] = (uint32_t)(n * 64 + ((c ^ ((n >> 1) & 3)) << 4));
        b_src_h[p] = g_bhi + n * 256 + c * 8;
        b_src_l[p] = g_blo + n * 256 + c * 8;
    }

    // ---- prologue: B chunk 0 in flight while A is converted ----
#pragma unroll
    for (int p = 0; p < 4; p++) {
        CP16(sb + VB(0, 0) + b_dst_off[p], (const void*)b_src_h[p]);
        CP16(sb + VB(0, 1) + b_dst_off[p], (const void*)b_src_l[p]);
    }
    CP_COMMIT();

    // ---- A: load 64m x 256k fp32, convert fp16, store swizzled (once) ----
#pragma unroll 4
    for (int p = 0; p < 16; p++) {
        int idx = tid + p * 256;                 // float4 id 0..4095
        int k = idx >> 4;
        int m4 = (idx & 15) << 2;
        float4 v = *(const float4*)(Ag + (long)k * HWSZ + m4);
        int c = m4 >> 3;
        uint32_t off = (uint32_t)(k * 128 + ((c ^ (k & 7)) << 4) + ((m4 & 4) << 1));
        *(uint2*)(smem + VA_OFF + off) = make_uint2(
            h2u(__float2half(v.x), __float2half(v.y)),
            h2u(__float2half(v.z), __float2half(v.w)));
    }

    // ---- ldsm offsets ----
    const int tile = lane >> 3;
    const int kl = (lane & 7) + ((tile & 2) << 2);      // k row within 16
    uint32_t aoff[2];                                    // per mf, at kc=0/ks=0
#pragma unroll
    for (int mf = 0; mf < 2; mf++) {
        int c = (warp_m * 32 + mf * 16 + ((tile & 1) << 3)) >> 3;
        aoff[mf] = (uint32_t)(kl * 128 + (((c ^ (kl & 7)) & 7) << 4));
    }
    uint32_t boff[4];                                    // per q, ks=0
#pragma unroll
    for (int q = 0; q < 4; q++) {
        int n = warp_n * 64 + q * 16 + ((tile & 1) << 3) + (lane & 7);
        int c = (tile & 2) >> 1;                         // ks adds via ^32
        boff[q] = (uint32_t)(n * 64 + ((c ^ ((n >> 1) & 3)) << 4));
    }

    float acc[2][8][4];
#pragma unroll
    for (int i = 0; i < 2; i++)
#pragma unroll
        for (int j = 0; j < 8; j++)
#pragma unroll
            for (int r = 0; r < 4; r++) acc[i][j][r] = 0.f;

    CP_WAIT0();
    __syncthreads();

    // ---- mainloop: 8 chunks of k=32 ----
    for (int kc = 0; kc < 8; kc++) {
        const int cur = kc & 1;
        if (kc < 7) {
            const int k0 = (kc + 1) * 32;
#pragma unroll
            for (int p = 0; p < 4; p++) {
                CP16(sb + VB(1 - cur, 0) + b_dst_off[p], (const void*)(b_src_h[p] + k0));
                CP16(sb + VB(1 - cur, 1) + b_dst_off[p], (const void*)(b_src_l[p] + k0));
            }
            CP_COMMIT();
        }

        const uint32_t Bh = sb + VB(cur, 0), Bl = sb + VB(cur, 1);
#pragma unroll
        for (int ks = 0; ks < 2; ks++) {
            // A frags (resident, single fp16 array)
            uint32_t a[2][4];
            const uint32_t akc = (uint32_t)((kc * 32 + ks * 16) * 128);
#pragma unroll
            for (int mf = 0; mf < 2; mf++)
                LDSM_T(a[mf], sb + VA_OFF + akc + aoff[mf]);

            const uint32_t ksx = (uint32_t)(ks << 5);    // swizzled k16 step
#pragma unroll
            for (int q = 0; q < 4; q++) {
                uint32_t bh[4], bl[4];
                LDSM(bh, Bh + (boff[q] ^ ksx));
                LDSM(bl, Bl + (boff[q] ^ ksx));
#pragma unroll
                for (int h = 0; h < 2; h++) {
                    const int nf = q * 2 + h;
#pragma unroll
                    for (int mf = 0; mf < 2; mf++) {
                        MMA_F16(acc[mf][nf], a[mf], bh[h], bh[h + 2]);
                        MMA_F16(acc[mf][nf], a[mf], bl[h], bl[h + 2]);
                    }
                }
            }
        }

        if (kc < 7) CP_WAIT0();
        __syncthreads();
    }

    // ---- epilogue: direct float2 stores ----
    float* vout = g_v + ((long)b * HWSZ + m0) * DD;
#pragma unroll
    for (int mf = 0; mf < 2; mf++) {
        int mrow = warp_m * 32 + mf * 16 + (lane >> 2);
#pragma unroll
        for (int nf = 0; nf < 8; nf++) {
            int n = warp_n * 64 + nf * 8 + (lane & 3) * 2;
            float2 bb = *(const float2*)(bias + n);
            *(float2*)(vout + (long)mrow * DD + n) =
                make_float2(acc[mf][nf][0] + bb.x, acc[mf][nf][1] + bb.y);
            *(float2*)(vout + (long)(mrow + 8) * DD + n) =
                make_float2(acc[mf][nf][2] + bb.x, acc[mf][nf][3] + bb.y);
        }
    }
}

// =====================================================================
// gemm_small: C[M x 256] = A[M x 256] @ W[256 x 256] + bias (+R)
// (bf16 3-term split — accuracy anchor for the small projections)
// =====================================================================
#define S_APITCH 72
#define S_BPITCH 136
#define S_ASZ    (64 * S_APITCH * 2)            // 9216
#define S_BSZ    (64 * S_BPITCH * 2)            // 17408
#define S_AB(buf, hl) (((buf) * 2 + (hl)) * S_ASZ)               // 0..36864
#define S_BB(buf, hl) (36864 + ((buf) * 2 + (hl)) * S_BSZ)       // ..106496
#define S_SMEM 106496

template <bool RES>
__global__ void __launch_bounds__(256) gemm_small(
    const float* __restrict__ A, const float* __restrict__ Wm,
    const float* __restrict__ bias, const float* __restrict__ Rm,
    float* __restrict__ C, int M)
{
    extern __shared__ char smem[];
    const uint32_t sb = smem_u32(smem);
    const int tid = threadIdx.x;
    const int lane = tid & 31;
    const int wid = tid >> 5;
    const int warp_m = wid & 1;
    const int warp_n = wid >> 1;
    const int n0 = blockIdx.x * 128;
    const int m0 = blockIdx.y * 64;

    const int tile = lane >> 3;
    uint32_t aoff[2];
#pragma unroll
    for (int mf = 0; mf < 2; mf++) {
        int ml = warp_m * 32 + mf * 16 + ((tile & 1) << 3) + (lane & 7);
        int kcol = (tile & 2) << 2;
        aoff[mf] = (uint32_t)(ml * S_APITCH + kcol) * 2;
    }
    uint32_t boff[2];
#pragma unroll
    for (int q = 0; q < 2; q++) {
        int kr = (lane & 7) + ((tile & 2) << 2);
        int nc = warp_n * 32 + q * 16 + ((tile & 1) << 3);
        boff[q] = (uint32_t)(kr * S_BPITCH + nc) * 2;
    }

    float acc[2][4][4];
#pragma unroll
    for (int i = 0; i < 2; i++)
#pragma unroll
        for (int j = 0; j < 4; j++)
#pragma unroll
            for (int r = 0; r < 4; r++) acc[i][j][r] = 0.f;

    float4 rA[4], rB[8];

    auto g_load = [&](int kc) {
        const int k0 = kc * 64;
#pragma unroll
        for (int p = 0; p < 4; p++) {
            int idx = tid + p * 256;
            int m = idx >> 4, k4 = (idx & 15) << 2;
            rA[p] = (m0 + m < M) ? *(const float4*)(A + (long)(m0 + m) * DD + k0 + k4)
                                 : make_float4(0.f, 0.f, 0.f, 0.f);
        }
#pragma unroll
        for (int p = 0; p < 8; p++) {
            int idx = tid + p * 256;
            int k = idx >> 5, n4 = (idx & 31) << 2;
            rB[p] = *(const float4*)(Wm + (long)(k0 + k) * DD + n0 + n4);
        }
    };
    auto s_store = [&](int buf) {
#pragma unroll
        for (int p = 0; p < 4; p++) {
            int idx = tid + p * 256;
            int m = idx >> 4, k4 = (idx & 15) << 2;
            split_store(smem + S_AB(buf, 0), smem + S_AB(buf, 1),
                        (uint32_t)(m * S_APITCH + k4) * 2, rA[p]);
        }
#pragma unroll
        for (int p = 0; p < 8; p++) {
            int idx = tid + p * 256;
            int k = idx >> 5, n4 = (idx & 31) << 2;
            split_store(smem + S_BB(buf, 0), smem + S_BB(buf, 1),
                        (uint32_t)(k * S_BPITCH + n4) * 2, rB[p]);
        }
    };

    g_load(0);
    s_store(0);
    __syncthreads();

    for (int kc = 0; kc < 4; kc++) {
        const int cur = kc & 1;
        if (kc < 3) g_load(kc + 1);

        const uint32_t Ah = sb + S_AB(cur, 0), Al = sb + S_AB(cur, 1);
        const uint32_t Bh = sb + S_BB(cur, 0), Bl = sb + S_BB(cur, 1);
#pragma unroll
        for (int ks = 0; ks < 4; ks++) {
            uint32_t ah[2][4], al[2][4], bh[2][4], bl[2][4];
#pragma unroll
            for (int mf = 0; mf < 2; mf++) {
                LDSM(ah[mf], Ah + aoff[mf] + ks * 32);
                LDSM(al[mf], Al + aoff[mf] + ks * 32);
            }
#pragma unroll
            for (int q = 0; q < 2; q++) {
                LDSM_T(bh[q], Bh + boff[q] + ks * (16 * S_BPITCH * 2));
                LDSM_T(bl[q], Bl + boff[q] + ks * (16 * S_BPITCH * 2));
            }
#pragma unroll
            for (int mf = 0; mf < 2; mf++)
#pragma unroll
                for (int nf = 0; nf < 4; nf++) {
                    int q = nf >> 1, h = nf & 1;
                    MMA_BF16(acc[mf][nf], ah[mf], bh[q][h], bh[q][h + 2]);
                    MMA_BF16(acc[mf][nf], ah[mf], bl[q][h], bl[q][h + 2]);
                    MMA_BF16(acc[mf][nf], al[mf], bh[q][h], bh[q][h + 2]);
                }
        }
        if (kc < 3) s_store(1 - cur);
        __syncthreads();
    }

#pragma unroll
    for (int mf = 0; mf < 2; mf++) {
        int mrow = warp_m * 32 + mf * 16 + (lane >> 2);
#pragma unroll
        for (int nf = 0; nf < 4; nf++) {
            int n = warp_n * 32 + nf * 8 + (lane & 3) * 2;
            float2 bb = *(const float2*)(bias + n0 + n);
            float2 s0 = make_float2(acc[mf][nf][0] + bb.x, acc[mf][nf][1] + bb.y);
            float2 s1 = make_float2(acc[mf][nf][2] + bb.x, acc[mf][nf][3] + bb.y);
            if (RES) {
                if (m0 + mrow < M) {
                    float2 r = *(const float2*)(Rm + (long)(m0 + mrow) * DD + n0 + n);
                    s0.x += r.x; s0.y += r.y;
                }
                if (m0 + mrow + 8 < M) {
                    float2 r = *(const float2*)(Rm + (long)(m0 + mrow + 8) * DD + n0 + n);
                    s1.x += r.x; s1.y += r.y;
                }
            }
            if (m0 + mrow < M)
                *(float2*)(C + (long)(m0 + mrow) * DD + n0 + n) = s0;
            if (m0 + mrow + 8 < M)
                *(float2*)(C + (long)(m0 + mrow + 8) * DD + n0 + n) = s1;
        }
    }
}

// ---------------- offsets + attention weights ----------------
__global__ __launch_bounds__(128) void offattn_kernel(
    const float* __restrict__ Woff, const float* __restrict__ boff,
    const float* __restrict__ Wattn, const float* __restrict__ battn)
{
    __shared__ float qs[256];
    __shared__ float lg[32];
    const int row = blockIdx.x;
    const int tid = threadIdx.x;
    const float* qr = g_q + (long)row * DD;
    qs[tid] = qr[tid];
    qs[tid + 128] = qr[tid + 128];
    __syncthreads();

    if (tid < 64) {
        float s = boff[tid];
#pragma unroll 8
        for (int k = 0; k < 256; k++) s = fmaf(qs[k], Woff[k * 64 + tid], s);
        g_off[(long)row * 64 + tid] = s;
    } else if (tid < 96) {
        int j = tid - 64;
        float s = battn[j];
#pragma unroll 8
        for (int k = 0; k < 256; k++) s = fmaf(qs[k], Wattn[k * 32 + j], s);
        lg[j] = s;
    }
    __syncthreads();

    if (tid < 32) {
        float x = lg[tid];
        float m = x;
        m = fmaxf(m, __shfl_xor_sync(0xffffffffu, m, 1));
        m = fmaxf(m, __shfl_xor_sync(0xffffffffu, m, 2));
        float e = expf(x - m);
        float s = e;
        s += __shfl_xor_sync(0xffffffffu, s, 1);
        s += __shfl_xor_sync(0xffffffffu, s, 2);
        g_aw[(long)row * 32 + tid] = e / s;
    }
}

// ---------------- Bezier + bilinear sampling + weighted sum ----------------
__global__ __launch_bounds__(256) void sample_kernel(
    const float* __restrict__ ctrl, const float* __restrict__ pc)
{
    __shared__ float s_ctrl[8];
    __shared__ float s_off[64];
    __shared__ float s_aw[32];
    __shared__ int   s_idx[320][4];
    __shared__ float s_w[320][4];

    const int bn = blockIdx.x;
    const int b = bn / NQ;
    const int tid = threadIdx.x;

    if (tid < 8)  s_ctrl[tid] = ctrl[(long)bn * 8 + tid];
    else if (tid >= 32 && tid < 96) s_off[tid - 32] = g_off[(long)bn * 64 + (tid - 32)];
    else if (tid >= 96 && tid < 128) s_aw[tid - 96] = g_aw[(long)bn * 32 + (tid - 96)];
    __syncthreads();

    const float p0 = pc[0], p1 = pc[1];
    const float invx = 1.f / (pc[3] - p0);
    const float invy = 1.f / (pc[4] - p1);

    for (int it = tid; it < 320; it += 256) {
        const int h = it / 40;
        const int kp = it - h * 40;
        const int k = kp >> 2;
        const int p = kp & 3;

        float t = (float)k * (1.0f / (NK - 1));
        float u = 1.f - t;
        float b0 = u * u * u, b1 = 3.f * u * u * t, b2 = 3.f * u * t * t, b3 = t * t * t;
        float px = b0 * s_ctrl[0] + b1 * s_ctrl[2] + b2 * s_ctrl[4] + b3 * s_ctrl[6];
        float py = b0 * s_ctrl[1] + b1 * s_ctrl[3] + b2 * s_ctrl[5] + b3 * s_ctrl[7];
        float nx = fminf(fmaxf((px - p0) * invx, 0.01f), 0.99f);
        float ny = fminf(fmaxf((py - p1) * invy, 0.01f), 0.99f);

        float gx = (nx + s_off[h * 8 + p * 2 + 0] * (1.f / WW)) * WW - 0.5f;
        float gy = (ny + s_off[h * 8 + p * 2 + 1] * (1.f / HH)) * HH - 0.5f;
        float fx = floorf(gx), fy = floorf(gy);
        float wx = gx - fx, wy = gy - fy;
        int xi = (int)fx, yi = (int)fy;
        float ap = s_aw[h * 4 + p];

#pragma unroll
        for (int c = 0; c < 4; c++) {
            int dx = c & 1, dy = c >> 1;
            int ix = xi + dx, iy = yi + dy;
            bool valid = (ix >= 0) & (ix < WW) & (iy >= 0) & (iy < HH);
            float wgt = valid ? ap * (dx ? wx : 1.f - wx) * (dy ? wy : 1.f - wy) : 0.f;
            int cx = min(max(ix, 0), WW - 1);
            int cy = min(max(iy, 0), HH - 1);
            s_w[it][c] = wgt;
            s_idx[it][c] = cy * WW + cx;
        }
    }
    __syncthreads();

    const int h = tid >> 5, lane = tid & 31;
    const float* vb = g_v + (long)b * HWSZ * DD + h * HDIM + lane;
    float acc = 0.f;
    const int base = h * 40;
#pragma unroll 4
    for (int i = 0; i < 40; i++) {
#pragma unroll
        for (int c = 0; c < 4; c++) {
            float w = s_w[base + i][c];
            int idx = s_idx[base + i][c];
            acc = fmaf(w, vb[(long)idx * DD], acc);
        }
    }
    g_s[(long)bn * DD + h * HDIM + lane] = acc;
}

// ---------------- launch ----------------
extern "C" void kernel_launch(void* const* d_in, const int* in_sizes, int n_in,
                              void* d_out, int out_size)
{
    const float* query = (const float*)d_in[0];
    const float* ctrl  = (const float*)d_in[1];
    const float* bev   = (const float*)d_in[2];
    const float* pc    = (const float*)d_in[4];
    const float* Wq    = (const float*)d_in[5];
    const float* bq    = (const float*)d_in[6];
    const float* Wv    = (const float*)d_in[7];
    const float* bv    = (const float*)d_in[8];
    const float* Woff  = (const float*)d_in[9];
    const float* boff  = (const float*)d_in[10];
    const float* Wattn = (const float*)d_in[11];
    const float* battn = (const float*)d_in[12];
    const float* Wmo   = (const float*)d_in[13];
    const float* bmo   = (const float*)d_in[14];
    const float* Wo    = (const float*)d_in[15];
    const float* bo    = (const float*)d_in[16];
    float* out = (float*)d_out;

    float *pq, *ps, *pt;
    cudaGetSymbolAddress((void**)&pq, g_q);
    cudaGetSymbolAddress((void**)&ps, g_s);
    cudaGetSymbolAddress((void**)&pt, g_t);

    cudaFuncSetAttribute(gemm_v, cudaFuncAttributeMaxDynamicSharedMemorySize, V_SMEM);
    cudaFuncSetAttribute(gemm_small<false>, cudaFuncAttributeMaxDynamicSharedMemorySize, S_SMEM);
    cudaFuncSetAttribute(gemm_small<true>, cudaFuncAttributeMaxDynamicSharedMemorySize, S_SMEM);

    const int Mq = BB * NQ;                     // 3600
    const dim3 sg_grid(2, (Mq + 63) / 64);      // 2 x 57

    // q = query @ Wq + bq
    gemm_small<false><<<sg_grid, 256, S_SMEM>>>(query, Wq, bq, nullptr, pq, Mq);

    // offsets + attention weights
    offattn_kernel<<<Mq, 128>>>(Woff, boff, Wattn, battn);

    // Wv -> WvT hi/lo (fp16 split)
    conv_wv<<<DD, 256>>>(Wv);

    // v = bev^T @ Wv + bv
    gemm_v<<<dim3(HWSZ / 64, BB), 256, V_SMEM>>>(bev, bv);

    // bezier + bilinear sampling + attention-weighted sum
    sample_kernel<<<BB * NQ, 256>>>(ctrl, pc);

    // t = s @ Wmo + bmo + q
    gemm_small<true><<<sg_grid, 256, S_SMEM>>>(ps, Wmo, bmo, pq, pt, Mq);

    // out = t @ Wo + bo
    gemm_small<false><<<sg_grid, 256, S_SMEM>>>(pt, Wo, bo, nullptr, out, Mq);
}

// round 8
// speedup vs baseline: 1.3378x; 1.0477x over previous
#include <cuda_runtime.h>
#include <cuda_bf16.h>
#include <cuda_fp16.h>
#include <cstdint>
#include <math.h>

// Problem constants (fixed shapes)
#define BB      4
#define NQ      900
#define DD      256
#define CH      256
#define HH      200
#define WW      200
#define HWSZ    40000
#define NHEADS  8
#define HDIM    32
#define NK      10
#define NPTS    4

// ---------------- scratch (device globals; no runtime allocation) ----------------
__device__ float g_q  [BB * NQ * DD];
__device__ __half g_vh[(long)BB * HWSZ * DD];    // projected BEV values (fp16)
__device__ float g_off[BB * NQ * NHEADS * NPTS * 2];
__device__ float g_aw [BB * NQ * NHEADS * NPTS];
__device__ float g_s  [BB * NQ * DD];
__device__ float g_t  [BB * NQ * DD];
__device__ __half g_bhi[DD * CH];                // WvT [n][k] hi (fp16)
__device__ __half g_blo[DD * CH];                // WvT [n][k] lo (fp16)

// ---------------- helpers ----------------
__device__ __forceinline__ uint32_t smem_u32(const void* p) {
    uint32_t a;
    asm("{ .reg .u64 t; cvta.to.shared.u64 t, %1; cvt.u32.u64 %0, t; }" : "=r"(a) : "l"(p));
    return a;
}
__device__ __forceinline__ uint32_t bf2u(__nv_bfloat16 a, __nv_bfloat16 b) {
    __nv_bfloat162 t(a, b);
    return *reinterpret_cast<uint32_t*>(&t);
}
__device__ __forceinline__ uint32_t h2u(__half a, __half b) {
    __half2 t(a, b);
    return *reinterpret_cast<uint32_t*>(&t);
}

#define LDSM_T(r, addr) \
    asm volatile("ldmatrix.sync.aligned.m8n8.x4.trans.shared.b16 {%0,%1,%2,%3}, [%4];" \
        : "=r"((r)[0]), "=r"((r)[1]), "=r"((r)[2]), "=r"((r)[3]) : "r"(addr))
#define LDSM(r, addr) \
    asm volatile("ldmatrix.sync.aligned.m8n8.x4.shared.b16 {%0,%1,%2,%3}, [%4];" \
        : "=r"((r)[0]), "=r"((r)[1]), "=r"((r)[2]), "=r"((r)[3]) : "r"(addr))
#define MMA_BF16(c, a, b0, b1) \
    asm volatile("mma.sync.aligned.m16n8k16.row.col.f32.bf16.bf16.f32 " \
        "{%0,%1,%2,%3},{%4,%5,%6,%7},{%8,%9},{%0,%1,%2,%3};" \
        : "+f"((c)[0]), "+f"((c)[1]), "+f"((c)[2]), "+f"((c)[3]) \
        : "r"((a)[0]), "r"((a)[1]), "r"((a)[2]), "r"((a)[3]), "r"(b0), "r"(b1))
#define MMA_F16(c, a, b0, b1) \
    asm volatile("mma.sync.aligned.m16n8k16.row.col.f32.f16.f16.f32 " \
        "{%0,%1,%2,%3},{%4,%5,%6,%7},{%8,%9},{%0,%1,%2,%3};" \
        : "+f"((c)[0]), "+f"((c)[1]), "+f"((c)[2]), "+f"((c)[3]) \
        : "r"((a)[0]), "r"((a)[1]), "r"((a)[2]), "r"((a)[3]), "r"(b0), "r"(b1))
#define CP16(dst, src) \
    asm volatile("cp.async.cg.shared.global [%0], [%1], 16;" :: "r"(dst), "l"(src))
#define CP_COMMIT()  asm volatile("cp.async.commit_group;" ::: "memory")
#define CP_WAIT0()   asm volatile("cp.async.wait_group 0;" ::: "memory")

__device__ __forceinline__ void split_store(char* dst_h, char* dst_l, uint32_t off, float4 v) {
    __nv_bfloat16 h0 = __float2bfloat16(v.x), h1 = __float2bfloat16(v.y);
    __nv_bfloat16 h2 = __float2bfloat16(v.z), h3 = __float2bfloat16(v.w);
    __nv_bfloat16 l0 = __float2bfloat16(v.x - __bfloat162float(h0));
    __nv_bfloat16 l1 = __float2bfloat16(v.y - __bfloat162float(h1));
    __nv_bfloat16 l2 = __float2bfloat16(v.z - __bfloat162float(h2));
    __nv_bfloat16 l3 = __float2bfloat16(v.w - __bfloat162float(h3));
    *(uint2*)(dst_h + off) = make_uint2(bf2u(h0, h1), bf2u(h2, h3));
    *(uint2*)(dst_l + off) = make_uint2(bf2u(l0, l1), bf2u(l2, l3));
}

// ---------------- Wv (K=256, N=256) -> WvT hi/lo fp16 [n][k] ----------------
__global__ __launch_bounds__(256) void conv_wv(const float* __restrict__ Wv)
{
    int idx = blockIdx.x * 256 + threadIdx.x;   // n*256 + k
    int n = idx >> 8, k = idx & 255;
    float v = Wv[k * DD + n];
    __half hi = __float2half(v);
    g_bhi[idx] = hi;
    g_blo[idx] = __float2half(v - __half2float(hi));
}

// =====================================================================
// gemm_v: v[b,m,:] = bev^T[b,m,:] @ WvT^T + bv  (HMMA fp16, 2-term B-split)
// CTA 64(m) x 256(n) FULL N. A fp16 resident in smem. B hi/lo streamed via
// cp.async in 8 chunks of k=32, double-buffered. 8 warps = 2m x 4n.
// q-loop software-pipelined (b-frag double buffer). Output: fp16 g_vh,
// staged via smem (pitch 528B, conflict-free) for full-line stores.
// =====================================================================
// A: row k = 128B (64 m-els fp16); 16B chunk c stored at c ^ (k&7).
// B: row n = 64B (32 k-els);       16B chunk c stored at c ^ ((n>>1)&3).
#define VA_OFF        0                                     // 32768 bytes
#define VB(buf, hl)   (32768 + ((buf) * 2 + (hl)) * 16384)  // ..98304
#define V_STG         32768                                 // epilogue stage (reuses B)
#define V_SMEM 98304

__global__ void __launch_bounds__(256, 2) gemm_v(
    const float* __restrict__ bev, const float* __restrict__ bias)
{
    extern __shared__ char smem[];
    const uint32_t sb = smem_u32(smem);
    const int tid = threadIdx.x;
    const int lane = tid & 31;
    const int wid = tid >> 5;
    const int warp_m = wid & 1;                  // 2 warps over m (32 each)
    const int warp_n = wid >> 1;                 // 4 warps over n (64 each)
    const int m0 = blockIdx.x * 64;
    const int b = blockIdx.y;

    const float* Ag = bev + (long)b * CH * HWSZ + m0;   // A[k][m], fp32 rows

    // ---- B cp.async addressing: chunk e = n*4 + c ; gmem offsets only ----
    uint32_t b_dst_off[4], b_goff[4];
#pragma unroll
    for (int p = 0; p < 4; p++) {
        int e = tid + p * 256;                   // 0..1023
        int n = e >> 2, c = e & 3;
        b_dst_off[p] = (uint32_t)(n * 64 + ((c ^ ((n >> 1) & 3)) << 4));
        b_goff[p] = (uint32_t)(n * 256 + c * 8);
    }

    // ---- prologue: B chunk 0 in flight while A is converted ----
#pragma unroll
    for (int p = 0; p < 4; p++) {
        CP16(sb + VB(0, 0) + b_dst_off[p], (const void*)(g_bhi + b_goff[p]));
        CP16(sb + VB(0, 1) + b_dst_off[p], (const void*)(g_blo + b_goff[p]));
    }
    CP_COMMIT();

    // ---- A: load 64m x 256k fp32, convert fp16, store swizzled (once) ----
#pragma unroll 4
    for (int p = 0; p < 16; p++) {
        int idx = tid + p * 256;                 // float4 id 0..4095
        int k = idx >> 4;
        int m4 = (idx & 15) << 2;
        float4 v = *(const float4*)(Ag + (long)k * HWSZ + m4);
        int c = m4 >> 3;
        uint32_t off = (uint32_t)(k * 128 + ((c ^ (k & 7)) << 4) + ((m4 & 4) << 1));
        *(uint2*)(smem + VA_OFF + off) = make_uint2(
            h2u(__float2half(v.x), __float2half(v.y)),
            h2u(__float2half(v.z), __float2half(v.w)));
    }

    // ---- ldsm offsets ----
    const int tile = lane >> 3;
    const int kl = (lane & 7) + ((tile & 2) << 2);      // k row within 16
    uint32_t aoff[2];
#pragma unroll
    for (int mf = 0; mf < 2; mf++) {
        int c = (warp_m * 32 + mf * 16 + ((tile & 1) << 3)) >> 3;
        aoff[mf] = (uint32_t)(kl * 128 + (((c ^ (kl & 7)) & 7) << 4));
    }
    uint32_t boff[4];
#pragma unroll
    for (int q = 0; q < 4; q++) {
        int n = warp_n * 64 + q * 16 + ((tile & 1) << 3) + (lane & 7);
        int c = (tile & 2) >> 1;
        boff[q] = (uint32_t)(n * 64 + ((c ^ ((n >> 1) & 3)) << 4));
    }

    float acc[2][8][4];
#pragma unroll
    for (int i = 0; i < 2; i++)
#pragma unroll
        for (int j = 0; j < 8; j++)
#pragma unroll
            for (int r = 0; r < 4; r++) acc[i][j][r] = 0.f;

    CP_WAIT0();
    __syncthreads();

    // ---- mainloop: 8 chunks of k=32, q-loop software-pipelined ----
    for (int kc = 0; kc < 8; kc++) {
        const int cur = kc & 1;
        if (kc < 7) {
            const uint32_t k0 = (uint32_t)((kc + 1) * 32);
#pragma unroll
            for (int p = 0; p < 4; p++) {
                CP16(sb + VB(1 - cur, 0) + b_dst_off[p], (const void*)(g_bhi + b_goff[p] + k0));
                CP16(sb + VB(1 - cur, 1) + b_dst_off[p], (const void*)(g_blo + b_goff[p] + k0));
            }
            CP_COMMIT();
        }

        const uint32_t Bh = sb + VB(cur, 0), Bl = sb + VB(cur, 1);
#pragma unroll
        for (int ks = 0; ks < 2; ks++) {
            uint32_t a[2][4];
            const uint32_t akc = (uint32_t)((kc * 32 + ks * 16) * 128);
#pragma unroll
            for (int mf = 0; mf < 2; mf++)
                LDSM_T(a[mf], sb + VA_OFF + akc + aoff[mf]);

            const uint32_t ksx = (uint32_t)(ks << 5);
            uint32_t bh[2][4], bl[2][4];          // double-buffered frags
            LDSM(bh[0], Bh + (boff[0] ^ ksx));
            LDSM(bl[0], Bl + (boff[0] ^ ksx));
#pragma unroll
            for (int q = 0; q < 4; q++) {
                const int bc = q & 1, bn_ = bc ^ 1;
                if (q < 3) {
                    LDSM(bh[bn_], Bh + (boff[q + 1] ^ ksx));
                    LDSM(bl[bn_], Bl + (boff[q + 1] ^ ksx));
                }
#pragma unroll
                for (int h = 0; h < 2; h++) {
                    const int nf = q * 2 + h;
#pragma unroll
                    for (int mf = 0; mf < 2; mf++) {
                        MMA_F16(acc[mf][nf], a[mf], bh[bc][h], bh[bc][h + 2]);
                        MMA_F16(acc[mf][nf], a[mf], bl[bc][h], bl[bc][h + 2]);
                    }
                }
            }
        }

        if (kc < 7) CP_WAIT0();
        __syncthreads();
    }

    // ---- epilogue: stage fp16 in smem (pitch 528B), then full-line stores ----
    char* stg = smem + V_STG;
#pragma unroll
    for (int mf = 0; mf < 2; mf++) {
        int mrow = warp_m * 32 + mf * 16 + (lane >> 2);
#pragma unroll
        for (int nf = 0; nf < 8; nf++) {
            int n = warp_n * 64 + nf * 8 + (lane & 3) * 2;
            float2 bb = *(const float2*)(bias + n);
            __half2 v0 = __floats2half2_rn(acc[mf][nf][0] + bb.x, acc[mf][nf][1] + bb.y);
            __half2 v1 = __floats2half2_rn(acc[mf][nf][2] + bb.x, acc[mf][nf][3] + bb.y);
            *(__half2*)(stg + mrow * 528 + n * 2) = v0;
            *(__half2*)(stg + (mrow + 8) * 528 + n * 2) = v1;
        }
    }
    __syncthreads();
    __half* vout = g_vh + ((long)b * HWSZ + m0) * DD;
#pragma unroll
    for (int i = 0; i < 8; i++) {
        int cid = tid + i * 256;                 // 0..2047
        int r = cid >> 5, c16 = cid & 31;
        *(uint4*)((char*)vout + (long)r * 512 + c16 * 16) =
            *(const uint4*)(stg + r * 528 + c16 * 16);
    }
}

// =====================================================================
// gemm_small: C[M x 256] = A[M x 256] @ W[256 x 256] + bias (+R)
// (bf16 3-term split — accuracy anchor for the small projections)
// =====================================================================
#define S_APITCH 72
#define S_BPITCH 136
#define S_ASZ    (64 * S_APITCH * 2)            // 9216
#define S_BSZ    (64 * S_BPITCH * 2)            // 17408
#define S_AB(buf, hl) (((buf) * 2 + (hl)) * S_ASZ)               // 0..36864
#define S_BB(buf, hl) (36864 + ((buf) * 2 + (hl)) * S_BSZ)       // ..106496
#define S_SMEM 106496

template <bool RES>
__global__ void __launch_bounds__(256) gemm_small(
    const float* __restrict__ A, const float* __restrict__ Wm,
    const float* __restrict__ bias, const float* __restrict__ Rm,
    float* __restrict__ C, int M)
{
    extern __shared__ char smem[];
    const uint32_t sb = smem_u32(smem);
    const int tid = threadIdx.x;
    const int lane = tid & 31;
    const int wid = tid >> 5;
    const int warp_m = wid & 1;
    const int warp_n = wid >> 1;
    const int n0 = blockIdx.x * 128;
    const int m0 = blockIdx.y * 64;

    const int tile = lane >> 3;
    uint32_t aoff[2];
#pragma unroll
    for (int mf = 0; mf < 2; mf++) {
        int ml = warp_m * 32 + mf * 16 + ((tile & 1) << 3) + (lane & 7);
        int kcol = (tile & 2) << 2;
        aoff[mf] = (uint32_t)(ml * S_APITCH + kcol) * 2;
    }
    uint32_t boff[2];
#pragma unroll
    for (int q = 0; q < 2; q++) {
        int kr = (lane & 7) + ((tile & 2) << 2);
        int nc = warp_n * 32 + q * 16 + ((tile & 1) << 3);
        boff[q] = (uint32_t)(kr * S_BPITCH + nc) * 2;
    }

    float acc[2][4][4];
#pragma unroll
    for (int i = 0; i < 2; i++)
#pragma unroll
        for (int j = 0; j < 4; j++)
#pragma unroll
            for (int r = 0; r < 4; r++) acc[i][j][r] = 0.f;

    float4 rA[4], rB[8];

    auto g_load = [&](int kc) {
        const int k0 = kc * 64;
#pragma unroll
        for (int p = 0; p < 4; p++) {
            int idx = tid + p * 256;
            int m = idx >> 4, k4 = (idx & 15) << 2;
            rA[p] = (m0 + m < M) ? *(const float4*)(A + (long)(m0 + m) * DD + k0 + k4)
                                 : make_float4(0.f, 0.f, 0.f, 0.f);
        }
#pragma unroll
        for (int p = 0; p < 8; p++) {
            int idx = tid + p * 256;
            int k = idx >> 5, n4 = (idx & 31) << 2;
            rB[p] = *(const float4*)(Wm + (long)(k0 + k) * DD + n0 + n4);
        }
    };
    auto s_store = [&](int buf) {
#pragma unroll
        for (int p = 0; p < 4; p++) {
            int idx = tid + p * 256;
            int m = idx >> 4, k4 = (idx & 15) << 2;
            split_store(smem + S_AB(buf, 0), smem + S_AB(buf, 1),
                        (uint32_t)(m * S_APITCH + k4) * 2, rA[p]);
        }
#pragma unroll
        for (int p = 0; p < 8; p++) {
            int idx = tid + p * 256;
            int k = idx >> 5, n4 = (idx & 31) << 2;
            split_store(smem + S_BB(buf, 0), smem + S_BB(buf, 1),
                        (uint32_t)(k * S_BPITCH + n4) * 2, rB[p]);
        }
    };

    g_load(0);
    s_store(0);
    __syncthreads();

    for (int kc = 0; kc < 4; kc++) {
        const int cur = kc & 1;
        if (kc < 3) g_load(kc + 1);

        const uint32_t Ah = sb + S_AB(cur, 0), Al = sb + S_AB(cur, 1);
        const uint32_t Bh = sb + S_BB(cur, 0), Bl = sb + S_BB(cur, 1);
#pragma unroll
        for (int ks = 0; ks < 4; ks++) {
            uint32_t ah[2][4], al[2][4], bh[2][4], bl[2][4];
#pragma unroll
            for (int mf = 0; mf < 2; mf++) {
                LDSM(ah[mf], Ah + aoff[mf] + ks * 32);
                LDSM(al[mf], Al + aoff[mf] + ks * 32);
            }
#pragma unroll
            for (int q = 0; q < 2; q++) {
                LDSM_T(bh[q], Bh + boff[q] + ks * (16 * S_BPITCH * 2));
                LDSM_T(bl[q], Bl + boff[q] + ks * (16 * S_BPITCH * 2));
            }
#pragma unroll
            for (int mf = 0; mf < 2; mf++)
#pragma unroll
                for (int nf = 0; nf < 4; nf++) {
                    int q = nf >> 1, h = nf & 1;
                    MMA_BF16(acc[mf][nf], ah[mf], bh[q][h], bh[q][h + 2]);
                    MMA_BF16(acc[mf][nf], ah[mf], bl[q][h], bl[q][h + 2]);
                    MMA_BF16(acc[mf][nf], al[mf], bh[q][h], bh[q][h + 2]);
                }
        }
        if (kc < 3) s_store(1 - cur);
        __syncthreads();
    }

#pragma unroll
    for (int mf = 0; mf < 2; mf++) {
        int mrow = warp_m * 32 + mf * 16 + (lane >> 2);
#pragma unroll
        for (int nf = 0; nf < 4; nf++) {
            int n = warp_n * 32 + nf * 8 + (lane & 3) * 2;
            float2 bb = *(const float2*)(bias + n0 + n);
            float2 s0 = make_float2(acc[mf][nf][0] + bb.x, acc[mf][nf][1] + bb.y);
            float2 s1 = make_float2(acc[mf][nf][2] + bb.x, acc[mf][nf][3] + bb.y);
            if (RES) {
                if (m0 + mrow < M) {
                    float2 r = *(const float2*)(Rm + (long)(m0 + mrow) * DD + n0 + n);
                    s0.x += r.x; s0.y += r.y;
                }
                if (m0 + mrow + 8 < M) {
                    float2 r = *(const float2*)(Rm + (long)(m0 + mrow + 8) * DD + n0 + n);
                    s1.x += r.x; s1.y += r.y;
                }
            }
            if (m0 + mrow < M)
                *(float2*)(C + (long)(m0 + mrow) * DD + n0 + n) = s0;
            if (m0 + mrow + 8 < M)
                *(float2*)(C + (long)(m0 + mrow + 8) * DD + n0 + n) = s1;
        }
    }
}

// ---------------- offsets + attention weights ----------------
__global__ __launch_bounds__(128) void offattn_kernel(
    const float* __restrict__ Woff, const float* __restrict__ boff,
    const float* __restrict__ Wattn, const float* __restrict__ battn)
{
    __shared__ float qs[256];
    __shared__ float lg[32];
    const int row = blockIdx.x;
    const int tid = threadIdx.x;
    const float* qr = g_q + (long)row * DD;
    qs[tid] = qr[tid];
    qs[tid + 128] = qr[tid + 128];
    __syncthreads();

    if (tid < 64) {
        float s = boff[tid];
#pragma unroll 8
        for (int k = 0; k < 256; k++) s = fmaf(qs[k], Woff[k * 64 + tid], s);
        g_off[(long)row * 64 + tid] = s;
    } else if (tid < 96) {
        int j = tid - 64;
        float s = battn[j];
#pragma unroll 8
        for (int k = 0; k < 256; k++) s = fmaf(qs[k], Wattn[k * 32 + j], s);
        lg[j] = s;
    }
    __syncthreads();

    if (tid < 32) {
        float x = lg[tid];
        float m = x;
        m = fmaxf(m, __shfl_xor_sync(0xffffffffu, m, 1));
        m = fmaxf(m, __shfl_xor_sync(0xffffffffu, m, 2));
        float e = expf(x - m);
        float s = e;
        s += __shfl_xor_sync(0xffffffffu, s, 1);
        s += __shfl_xor_sync(0xffffffffu, s, 2);
        g_aw[(long)row * 32 + tid] = e / s;
    }
}

// ---------------- Bezier + bilinear sampling + weighted sum ----------------
__global__ __launch_bounds__(256) void sample_kernel(
    const float* __restrict__ ctrl, const float* __restrict__ pc)
{
    __shared__ float s_ctrl[8];
    __shared__ float s_off[64];
    __shared__ float s_aw[32];
    __shared__ int   s_idx[320][4];
    __shared__ float s_w[320][4];

    const int bn = blockIdx.x;
    const int b = bn / NQ;
    const int tid = threadIdx.x;

    if (tid < 8)  s_ctrl[tid] = ctrl[(long)bn * 8 + tid];
    else if (tid >= 32 && tid < 96) s_off[tid - 32] = g_off[(long)bn * 64 + (tid - 32)];
    else if (tid >= 96 && tid < 128) s_aw[tid - 96] = g_aw[(long)bn * 32 + (tid - 96)];
    __syncthreads();

    const float p0 = pc[0], p1 = pc[1];
    const float invx = 1.f / (pc[3] - p0);
    const float invy = 1.f / (pc[4] - p1);

    for (int it = tid; it < 320; it += 256) {
        const int h = it / 40;
        const int kp = it - h * 40;
        const int k = kp >> 2;
        const int p = kp & 3;

        float t = (float)k * (1.0f / (NK - 1));
        float u = 1.f - t;
        float b0 = u * u * u, b1 = 3.f * u * u * t, b2 = 3.f * u * t * t, b3 = t * t * t;
        float px = b0 * s_ctrl[0] + b1 * s_ctrl[2] + b2 * s_ctrl[4] + b3 * s_ctrl[6];
        float py = b0 * s_ctrl[1] + b1 * s_ctrl[3] + b2 * s_ctrl[5] + b3 * s_ctrl[7];
        float nx = fminf(fmaxf((px - p0) * invx, 0.01f), 0.99f);
        float ny = fminf(fmaxf((py - p1) * invy, 0.01f), 0.99f);

        float gx = (nx + s_off[h * 8 + p * 2 + 0] * (1.f / WW)) * WW - 0.5f;
        float gy = (ny + s_off[h * 8 + p * 2 + 1] * (1.f / HH)) * HH - 0.5f;
        float fx = floorf(gx), fy = floorf(gy);
        float wx = gx - fx, wy = gy - fy;
        int xi = (int)fx, yi = (int)fy;
        float ap = s_aw[h * 4 + p];

#pragma unroll
        for (int c = 0; c < 4; c++) {
            int dx = c & 1, dy = c >> 1;
            int ix = xi + dx, iy = yi + dy;
            bool valid = (ix >= 0) & (ix < WW) & (iy >= 0) & (iy < HH);
            float wgt = valid ? ap * (dx ? wx : 1.f - wx) * (dy ? wy : 1.f - wy) : 0.f;
            int cx = min(max(ix, 0), WW - 1);
            int cy = min(max(iy, 0), HH - 1);
            s_w[it][c] = wgt;
            s_idx[it][c] = cy * WW + cx;
        }
    }
    __syncthreads();

    const int h = tid >> 5, lane = tid & 31;
    const __half* vb = g_vh + (long)b * HWSZ * DD + h * HDIM + lane;
    float acc = 0.f;
    const int base = h * 40;
#pragma unroll 4
    for (int i = 0; i < 40; i++) {
#pragma unroll
        for (int c = 0; c < 4; c++) {
            float w = s_w[base + i][c];
            int idx = s_idx[base + i][c];
            acc = fmaf(w, __half2float(vb[(long)idx * DD]), acc);
        }
    }
    g_s[(long)bn * DD + h * HDIM + lane] = acc;
}

// ---------------- launch ----------------
extern "C" void kernel_launch(void* const* d_in, const int* in_sizes, int n_in,
                              void* d_out, int out_size)
{
    const float* query = (const float*)d_in[0];
    const float* ctrl  = (const float*)d_in[1];
    const float* bev   = (const float*)d_in[2];
    const float* pc    = (const float*)d_in[4];
    const float* Wq    = (const float*)d_in[5];
    const float* bq    = (const float*)d_in[6];
    const float* Wv    = (const float*)d_in[7];
    const float* bv    = (const float*)d_in[8];
    const float* Woff  = (const float*)d_in[9];
    const float* boff  = (const float*)d_in[10];
    const float* Wattn = (const float*)d_in[11];
    const float* battn = (const float*)d_in[12];
    const float* Wmo   = (const float*)d_in[13];
    const float* bmo   = (const float*)d_in[14];
    const float* Wo    = (const float*)d_in[15];
    const float* bo    = (const float*)d_in[16];
    float* out = (float*)d_out;

    float *pq, *ps, *pt;
    cudaGetSymbolAddress((void**)&pq, g_q);
    cudaGetSymbolAddress((void**)&ps, g_s);
    cudaGetSymbolAddress((void**)&pt, g_t);

    cudaFuncSetAttribute(gemm_v, cudaFuncAttributeMaxDynamicSharedMemorySize, V_SMEM);
    cudaFuncSetAttribute(gemm_small<false>, cudaFuncAttributeMaxDynamicSharedMemorySize, S_SMEM);
    cudaFuncSetAttribute(gemm_small<true>, cudaFuncAttributeMaxDynamicSharedMemorySize, S_SMEM);

    const int Mq = BB * NQ;                     // 3600
    const dim3 sg_grid(2, (Mq + 63) / 64);      // 2 x 57

    // q = query @ Wq + bq
    gemm_small<false><<<sg_grid, 256, S_SMEM>>>(query, Wq, bq, nullptr, pq, Mq);

    // offsets + attention weights
    offattn_kernel<<<Mq, 128>>>(Woff, boff, Wattn, battn);

    // Wv -> WvT hi/lo (fp16 split)
    conv_wv<<<DD, 256>>>(Wv);

    // v = bev^T @ Wv + bv  (fp16 output)
    gemm_v<<<dim3(HWSZ / 64, BB), 256, V_SMEM>>>(bev, bv);

    // bezier + bilinear sampling + attention-weighted sum
    sample_kernel<<<BB * NQ, 256>>>(ctrl, pc);

    // t = s @ Wmo + bmo + q
    gemm_small<true><<<sg_grid, 256, S_SMEM>>>(ps, Wmo, bmo, pq, pt, Mq);

    // out = t @ Wo + bo
    gemm_small<false><<<sg_grid, 256, S_SMEM>>>(pt, Wo, bo, nullptr, out, Mq);
}

// round 9
// speedup vs baseline: 1.7729x; 1.3252x over previous
#include <cuda_runtime.h>
#include <cuda_bf16.h>
#include <cuda_fp16.h>
#include <cstdint>
#include <math.h>

// Problem constants (fixed shapes)
#define BB      4
#define NQ      900
#define DD      256
#define CH      256
#define HH      200
#define WW      200
#define HWSZ    40000
#define NHEADS  8
#define HDIM    32
#define NK      10
#define NPTS    4

// ---------------- scratch (device globals; no runtime allocation) ----------------
__device__ float g_q  [BB * NQ * DD];
__device__ __half g_vh[(long)BB * HWSZ * DD];    // projected BEV values (fp16)
__device__ float g_off[BB * NQ * NHEADS * NPTS * 2];
__device__ float g_aw [BB * NQ * NHEADS * NPTS];
__device__ float g_s  [BB * NQ * DD];
__device__ float g_t  [BB * NQ * DD];
__device__ __half g_bhi[DD * CH];                // WvT [n][k] fp16

// ---------------- helpers ----------------
__device__ __forceinline__ uint32_t smem_u32(const void* p) {
    uint32_t a;
    asm("{ .reg .u64 t; cvta.to.shared.u64 t, %1; cvt.u32.u64 %0, t; }" : "=r"(a) : "l"(p));
    return a;
}
__device__ __forceinline__ uint32_t bf2u(__nv_bfloat16 a, __nv_bfloat16 b) {
    __nv_bfloat162 t(a, b);
    return *reinterpret_cast<uint32_t*>(&t);
}
__device__ __forceinline__ uint32_t h2u(__half a, __half b) {
    __half2 t(a, b);
    return *reinterpret_cast<uint32_t*>(&t);
}

#define LDSM_T(r, addr) \
    asm volatile("ldmatrix.sync.aligned.m8n8.x4.trans.shared.b16 {%0,%1,%2,%3}, [%4];" \
        : "=r"((r)[0]), "=r"((r)[1]), "=r"((r)[2]), "=r"((r)[3]) : "r"(addr))
#define LDSM(r, addr) \
    asm volatile("ldmatrix.sync.aligned.m8n8.x4.shared.b16 {%0,%1,%2,%3}, [%4];" \
        : "=r"((r)[0]), "=r"((r)[1]), "=r"((r)[2]), "=r"((r)[3]) : "r"(addr))
#define MMA_BF16(c, a, b0, b1) \
    asm volatile("mma.sync.aligned.m16n8k16.row.col.f32.bf16.bf16.f32 " \
        "{%0,%1,%2,%3},{%4,%5,%6,%7},{%8,%9},{%0,%1,%2,%3};" \
        : "+f"((c)[0]), "+f"((c)[1]), "+f"((c)[2]), "+f"((c)[3]) \
        : "r"((a)[0]), "r"((a)[1]), "r"((a)[2]), "r"((a)[3]), "r"(b0), "r"(b1))
#define MMA_F16(c, a, b0, b1) \
    asm volatile("mma.sync.aligned.m16n8k16.row.col.f32.f16.f16.f32 " \
        "{%0,%1,%2,%3},{%4,%5,%6,%7},{%8,%9},{%0,%1,%2,%3};" \
        : "+f"((c)[0]), "+f"((c)[1]), "+f"((c)[2]), "+f"((c)[3]) \
        : "r"((a)[0]), "r"((a)[1]), "r"((a)[2]), "r"((a)[3]), "r"(b0), "r"(b1))
#define CP16(dst, src) \
    asm volatile("cp.async.cg.shared.global [%0], [%1], 16;" :: "r"(dst), "l"(src))
#define CP_COMMIT()  asm volatile("cp.async.commit_group;" ::: "memory")
#define CP_WAIT0()   asm volatile("cp.async.wait_group 0;" ::: "memory")

__device__ __forceinline__ void split_store(char* dst_h, char* dst_l, uint32_t off, float4 v) {
    __nv_bfloat16 h0 = __float2bfloat16(v.x), h1 = __float2bfloat16(v.y);
    __nv_bfloat16 h2 = __float2bfloat16(v.z), h3 = __float2bfloat16(v.w);
    __nv_bfloat16 l0 = __float2bfloat16(v.x - __bfloat162float(h0));
    __nv_bfloat16 l1 = __float2bfloat16(v.y - __bfloat162float(h1));
    __nv_bfloat16 l2 = __float2bfloat16(v.z - __bfloat162float(h2));
    __nv_bfloat16 l3 = __float2bfloat16(v.w - __bfloat162float(h3));
    *(uint2*)(dst_h + off) = make_uint2(bf2u(h0, h1), bf2u(h2, h3));
    *(uint2*)(dst_l + off) = make_uint2(bf2u(l0, l1), bf2u(l2, l3));
}

// ---------------- Wv (K=256, N=256) -> WvT fp16 [n][k] ----------------
__global__ __launch_bounds__(256) void conv_wv(const float* __restrict__ Wv)
{
    int idx = blockIdx.x * 256 + threadIdx.x;   // n*256 + k
    int n = idx >> 8, k = idx & 255;
    g_bhi[idx] = __float2half(Wv[k * DD + n]);
}

// =====================================================================
// gemm_v: v[b,m,:] = bev^T[b,m,:] @ WvT^T + bv  (HMMA fp16 x fp16, fp32 acc)
// CTA 64(m) x 256(n) FULL N. A fp16 resident in smem. B fp16 streamed via
// cp.async in 8 chunks of k=32, double-buffered. 8 warps = 2m x 4n.
// q-loop software-pipelined. Output fp16 g_vh staged via smem.
// =====================================================================
// A: row k = 128B (64 m-els fp16); 16B chunk c stored at c ^ (k&7).
// B: row n = 64B (32 k-els);       16B chunk c stored at c ^ ((n>>1)&3).
#define VA_OFF        0                                     // 32768 bytes
#define VB(buf)       (32768 + (buf) * 16384)               // ..65536
#define V_STG         32768                                 // epilogue stage (64*528=33792)
#define V_SMEM 66560

__global__ void __launch_bounds__(256, 2) gemm_v(
    const float* __restrict__ bev, const float* __restrict__ bias)
{
    extern __shared__ char smem[];
    const uint32_t sb = smem_u32(smem);
    const int tid = threadIdx.x;
    const int lane = tid & 31;
    const int wid = tid >> 5;
    const int warp_m = wid & 1;                  // 2 warps over m (32 each)
    const int warp_n = wid >> 1;                 // 4 warps over n (64 each)
    const int m0 = blockIdx.x * 64;
    const int b = blockIdx.y;

    const float* Ag = bev + (long)b * CH * HWSZ + m0;   // A[k][m], fp32 rows

    // ---- B cp.async addressing: chunk e = n*4 + c ----
    uint32_t b_dst_off[4], b_goff[4];
#pragma unroll
    for (int p = 0; p < 4; p++) {
        int e = tid + p * 256;                   // 0..1023
        int n = e >> 2, c = e & 3;
        b_dst_off[p] = (uint32_t)(n * 64 + ((c ^ ((n >> 1) & 3)) << 4));
        b_goff[p] = (uint32_t)(n * 256 + c * 8);
    }

    // ---- prologue: B chunk 0 in flight while A is converted ----
#pragma unroll
    for (int p = 0; p < 4; p++)
        CP16(sb + VB(0) + b_dst_off[p], (const void*)(g_bhi + b_goff[p]));
    CP_COMMIT();

    // ---- A: load 64m x 256k fp32, convert fp16, store swizzled (once) ----
#pragma unroll 4
    for (int p = 0; p < 16; p++) {
        int idx = tid + p * 256;                 // float4 id 0..4095
        int k = idx >> 4;
        int m4 = (idx & 15) << 2;
        float4 v = *(const float4*)(Ag + (long)k * HWSZ + m4);
        int c = m4 >> 3;
        uint32_t off = (uint32_t)(k * 128 + ((c ^ (k & 7)) << 4) + ((m4 & 4) << 1));
        *(uint2*)(smem + VA_OFF + off) = make_uint2(
            h2u(__float2half(v.x), __float2half(v.y)),
            h2u(__float2half(v.z), __float2half(v.w)));
    }

    // ---- ldsm offsets ----
    const int tile = lane >> 3;
    const int kl = (lane & 7) + ((tile & 2) << 2);      // k row within 16
    uint32_t aoff[2];
#pragma unroll
    for (int mf = 0; mf < 2; mf++) {
        int c = (warp_m * 32 + mf * 16 + ((tile & 1) << 3)) >> 3;
        aoff[mf] = (uint32_t)(kl * 128 + (((c ^ (kl & 7)) & 7) << 4));
    }
    uint32_t boff[4];
#pragma unroll
    for (int q = 0; q < 4; q++) {
        int n = warp_n * 64 + q * 16 + ((tile & 1) << 3) + (lane & 7);
        int c = (tile & 2) >> 1;
        boff[q] = (uint32_t)(n * 64 + ((c ^ ((n >> 1) & 3)) << 4));
    }

    float acc[2][8][4];
#pragma unroll
    for (int i = 0; i < 2; i++)
#pragma unroll
        for (int j = 0; j < 8; j++)
#pragma unroll
            for (int r = 0; r < 4; r++) acc[i][j][r] = 0.f;

    CP_WAIT0();
    __syncthreads();

    // ---- mainloop: 8 chunks of k=32, q-loop software-pipelined ----
    for (int kc = 0; kc < 8; kc++) {
        const int cur = kc & 1;
        if (kc < 7) {
            const uint32_t k0 = (uint32_t)((kc + 1) * 32);
#pragma unroll
            for (int p = 0; p < 4; p++)
                CP16(sb + VB(1 - cur) + b_dst_off[p], (const void*)(g_bhi + b_goff[p] + k0));
            CP_COMMIT();
        }

        const uint32_t Bh = sb + VB(cur);
#pragma unroll
        for (int ks = 0; ks < 2; ks++) {
            uint32_t a[2][4];
            const uint32_t akc = (uint32_t)((kc * 32 + ks * 16) * 128);
#pragma unroll
            for (int mf = 0; mf < 2; mf++)
                LDSM_T(a[mf], sb + VA_OFF + akc + aoff[mf]);

            const uint32_t ksx = (uint32_t)(ks << 5);
            uint32_t bh[2][4];                    // double-buffered frags
            LDSM(bh[0], Bh + (boff[0] ^ ksx));
#pragma unroll
            for (int q = 0; q < 4; q++) {
                const int bc = q & 1, bn_ = bc ^ 1;
                if (q < 3)
                    LDSM(bh[bn_], Bh + (boff[q + 1] ^ ksx));
#pragma unroll
                for (int h = 0; h < 2; h++) {
                    const int nf = q * 2 + h;
#pragma unroll
                    for (int mf = 0; mf < 2; mf++)
                        MMA_F16(acc[mf][nf], a[mf], bh[bc][h], bh[bc][h + 2]);
                }
            }
        }

        if (kc < 7) CP_WAIT0();
        __syncthreads();
    }

    // ---- epilogue: stage fp16 in smem (pitch 528B), then full-line stores ----
    char* stg = smem + V_STG;
#pragma unroll
    for (int mf = 0; mf < 2; mf++) {
        int mrow = warp_m * 32 + mf * 16 + (lane >> 2);
#pragma unroll
        for (int nf = 0; nf < 8; nf++) {
            int n = warp_n * 64 + nf * 8 + (lane & 3) * 2;
            float2 bb = *(const float2*)(bias + n);
            __half2 v0 = __floats2half2_rn(acc[mf][nf][0] + bb.x, acc[mf][nf][1] + bb.y);
            __half2 v1 = __floats2half2_rn(acc[mf][nf][2] + bb.x, acc[mf][nf][3] + bb.y);
            *(__half2*)(stg + mrow * 528 + n * 2) = v0;
            *(__half2*)(stg + (mrow + 8) * 528 + n * 2) = v1;
        }
    }
    __syncthreads();
    __half* vout = g_vh + ((long)b * HWSZ + m0) * DD;
#pragma unroll
    for (int i = 0; i < 8; i++) {
        int cid = tid + i * 256;                 // 0..2047
        int r = cid >> 5, c16 = cid & 31;
        *(uint4*)((char*)vout + (long)r * 512 + c16 * 16) =
            *(const uint4*)(stg + r * 528 + c16 * 16);
    }
}

// =====================================================================
// gemm_small: C[M x 256] = A[M x 256] @ W[256 x 256] + bias (+R)
// (bf16 3-term split — accuracy anchor for the small projections)
// =====================================================================
#define S_APITCH 72
#define S_BPITCH 136
#define S_ASZ    (64 * S_APITCH * 2)            // 9216
#define S_BSZ    (64 * S_BPITCH * 2)            // 17408
#define S_AB(buf, hl) (((buf) * 2 + (hl)) * S_ASZ)               // 0..36864
#define S_BB(buf, hl) (36864 + ((buf) * 2 + (hl)) * S_BSZ)       // ..106496
#define S_SMEM 106496

template <bool RES>
__global__ void __launch_bounds__(256) gemm_small(
    const float* __restrict__ A, const float* __restrict__ Wm,
    const float* __restrict__ bias, const float* __restrict__ Rm,
    float* __restrict__ C, int M)
{
    extern __shared__ char smem[];
    const uint32_t sb = smem_u32(smem);
    const int tid = threadIdx.x;
    const int lane = tid & 31;
    const int wid = tid >> 5;
    const int warp_m = wid & 1;
    const int warp_n = wid >> 1;
    const int n0 = blockIdx.x * 128;
    const int m0 = blockIdx.y * 64;

    const int tile = lane >> 3;
    uint32_t aoff[2];
#pragma unroll
    for (int mf = 0; mf < 2; mf++) {
        int ml = warp_m * 32 + mf * 16 + ((tile & 1) << 3) + (lane & 7);
        int kcol = (tile & 2) << 2;
        aoff[mf] = (uint32_t)(ml * S_APITCH + kcol) * 2;
    }
    uint32_t boff[2];
#pragma unroll
    for (int q = 0; q < 2; q++) {
        int kr = (lane & 7) + ((tile & 2) << 2);
        int nc = warp_n * 32 + q * 16 + ((tile & 1) << 3);
        boff[q] = (uint32_t)(kr * S_BPITCH + nc) * 2;
    }

    float acc[2][4][4];
#pragma unroll
    for (int i = 0; i < 2; i++)
#pragma unroll
        for (int j = 0; j < 4; j++)
#pragma unroll
            for (int r = 0; r < 4; r++) acc[i][j][r] = 0.f;

    float4 rA[4], rB[8];

    auto g_load = [&](int kc) {
        const int k0 = kc * 64;
#pragma unroll
        for (int p = 0; p < 4; p++) {
            int idx = tid + p * 256;
            int m = idx >> 4, k4 = (idx & 15) << 2;
            rA[p] = (m0 + m < M) ? *(const float4*)(A + (long)(m0 + m) * DD + k0 + k4)
                                 : make_float4(0.f, 0.f, 0.f, 0.f);
        }
#pragma unroll
        for (int p = 0; p < 8; p++) {
            int idx = tid + p * 256;
            int k = idx >> 5, n4 = (idx & 31) << 2;
            rB[p] = *(const float4*)(Wm + (long)(k0 + k) * DD + n0 + n4);
        }
    };
    auto s_store = [&](int buf) {
#pragma unroll
        for (int p = 0; p < 4; p++) {
            int idx = tid + p * 256;
            int m = idx >> 4, k4 = (idx & 15) << 2;
            split_store(smem + S_AB(buf, 0), smem + S_AB(buf, 1),
                        (uint32_t)(m * S_APITCH + k4) * 2, rA[p]);
        }
#pragma unroll
        for (int p = 0; p < 8; p++) {
            int idx = tid + p * 256;
            int k = idx >> 5, n4 = (idx & 31) << 2;
            split_store(smem + S_BB(buf, 0), smem + S_BB(buf, 1),
                        (uint32_t)(k * S_BPITCH + n4) * 2, rB[p]);
        }
    };

    g_load(0);
    s_store(0);
    __syncthreads();

    for (int kc = 0; kc < 4; kc++) {
        const int cur = kc & 1;
        if (kc < 3) g_load(kc + 1);

        const uint32_t Ah = sb + S_AB(cur, 0), Al = sb + S_AB(cur, 1);
        const uint32_t Bh = sb + S_BB(cur, 0), Bl = sb + S_BB(cur, 1);
#pragma unroll
        for (int ks = 0; ks < 4; ks++) {
            uint32_t ah[2][4], al[2][4], bh[2][4], bl[2][4];
#pragma unroll
            for (int mf = 0; mf < 2; mf++) {
                LDSM(ah[mf], Ah + aoff[mf] + ks * 32);
                LDSM(al[mf], Al + aoff[mf] + ks * 32);
            }
#pragma unroll
            for (int q = 0; q < 2; q++) {
                LDSM_T(bh[q], Bh + boff[q] + ks * (16 * S_BPITCH * 2));
                LDSM_T(bl[q], Bl + boff[q] + ks * (16 * S_BPITCH * 2));
            }
#pragma unroll
            for (int mf = 0; mf < 2; mf++)
#pragma unroll
                for (int nf = 0; nf < 4; nf++) {
                    int q = nf >> 1, h = nf & 1;
                    MMA_BF16(acc[mf][nf], ah[mf], bh[q][h], bh[q][h + 2]);
                    MMA_BF16(acc[mf][nf], ah[mf], bl[q][h], bl[q][h + 2]);
                    MMA_BF16(acc[mf][nf], al[mf], bh[q][h], bh[q][h + 2]);
                }
        }
        if (kc < 3) s_store(1 - cur);
        __syncthreads();
    }

#pragma unroll
    for (int mf = 0; mf < 2; mf++) {
        int mrow = warp_m * 32 + mf * 16 + (lane >> 2);
#pragma unroll
        for (int nf = 0; nf < 4; nf++) {
            int n = warp_n * 32 + nf * 8 + (lane & 3) * 2;
            float2 bb = *(const float2*)(bias + n0 + n);
            float2 s0 = make_float2(acc[mf][nf][0] + bb.x, acc[mf][nf][1] + bb.y);
            float2 s1 = make_float2(acc[mf][nf][2] + bb.x, acc[mf][nf][3] + bb.y);
            if (RES) {
                if (m0 + mrow < M) {
                    float2 r = *(const float2*)(Rm + (long)(m0 + mrow) * DD + n0 + n);
                    s0.x += r.x; s0.y += r.y;
                }
                if (m0 + mrow + 8 < M) {
                    float2 r = *(const float2*)(Rm + (long)(m0 + mrow + 8) * DD + n0 + n);
                    s1.x += r.x; s1.y += r.y;
                }
            }
            if (m0 + mrow < M)
                *(float2*)(C + (long)(m0 + mrow) * DD + n0 + n) = s0;
            if (m0 + mrow + 8 < M)
                *(float2*)(C + (long)(m0 + mrow + 8) * DD + n0 + n) = s1;
        }
    }
}

// ---------------- offsets + attention weights ----------------
__global__ __launch_bounds__(128) void offattn_kernel(
    const float* __restrict__ Woff, const float* __restrict__ boff,
    const float* __restrict__ Wattn, const float* __restrict__ battn)
{
    __shared__ float qs[256];
    __shared__ float lg[32];
    const int row = blockIdx.x;
    const int tid = threadIdx.x;
    const float* qr = g_q + (long)row * DD;
    qs[tid] = qr[tid];
    qs[tid + 128] = qr[tid + 128];
    __syncthreads();

    if (tid < 64) {
        float s = boff[tid];
#pragma unroll 8
        for (int k = 0; k < 256; k++) s = fmaf(qs[k], Woff[k * 64 + tid], s);
        g_off[(long)row * 64 + tid] = s;
    } else if (tid < 96) {
        int j = tid - 64;
        float s = battn[j];
#pragma unroll 8
        for (int k = 0; k < 256; k++) s = fmaf(qs[k], Wattn[k * 32 + j], s);
        lg[j] = s;
    }
    __syncthreads();

    if (tid < 32) {
        float x = lg[tid];
        float m = x;
        m = fmaxf(m, __shfl_xor_sync(0xffffffffu, m, 1));
        m = fmaxf(m, __shfl_xor_sync(0xffffffffu, m, 2));
        float e = expf(x - m);
        float s = e;
        s += __shfl_xor_sync(0xffffffffu, s, 1);
        s += __shfl_xor_sync(0xffffffffu, s, 2);
        g_aw[(long)row * 32 + tid] = e / s;
    }
}

// ---------------- Bezier + bilinear sampling + weighted sum ----------------
__global__ __launch_bounds__(256) void sample_kernel(
    const float* __restrict__ ctrl, const float* __restrict__ pc)
{
    __shared__ float s_ctrl[8];
    __shared__ float s_off[64];
    __shared__ float s_aw[32];
    __shared__ int   s_idx[320][4];
    __shared__ float s_w[320][4];

    const int bn = blockIdx.x;
    const int b = bn / NQ;
    const int tid = threadIdx.x;

    if (tid < 8)  s_ctrl[tid] = ctrl[(long)bn * 8 + tid];
    else if (tid >= 32 && tid < 96) s_off[tid - 32] = g_off[(long)bn * 64 + (tid - 32)];
    else if (tid >= 96 && tid < 128) s_aw[tid - 96] = g_aw[(long)bn * 32 + (tid - 96)];
    __syncthreads();

    const float p0 = pc[0], p1 = pc[1];
    const float invx = 1.f / (pc[3] - p0);
    const float invy = 1.f / (pc[4] - p1);

    for (int it = tid; it < 320; it += 256) {
        const int h = it / 40;
        const int kp = it - h * 40;
        const int k = kp >> 2;
        const int p = kp & 3;

        float t = (float)k * (1.0f / (NK - 1));
        float u = 1.f - t;
        float b0 = u * u * u, b1 = 3.f * u * u * t, b2 = 3.f * u * t * t, b3 = t * t * t;
        float px = b0 * s_ctrl[0] + b1 * s_ctrl[2] + b2 * s_ctrl[4] + b3 * s_ctrl[6];
        float py = b0 * s_ctrl[1] + b1 * s_ctrl[3] + b2 * s_ctrl[5] + b3 * s_ctrl[7];
        float nx = fminf(fmaxf((px - p0) * invx, 0.01f), 0.99f);
        float ny = fminf(fmaxf((py - p1) * invy, 0.01f), 0.99f);

        float gx = (nx + s_off[h * 8 + p * 2 + 0] * (1.f / WW)) * WW - 0.5f;
        float gy = (ny + s_off[h * 8 + p * 2 + 1] * (1.f / HH)) * HH - 0.5f;
        float fx = floorf(gx), fy = floorf(gy);
        float wx = gx - fx, wy = gy - fy;
        int xi = (int)fx, yi = (int)fy;
        float ap = s_aw[h * 4 + p];

#pragma unroll
        for (int c = 0; c < 4; c++) {
            int dx = c & 1, dy = c >> 1;
            int ix = xi + dx, iy = yi + dy;
            bool valid = (ix >= 0) & (ix < WW) & (iy >= 0) & (iy < HH);
            float wgt = valid ? ap * (dx ? wx : 1.f - wx) * (dy ? wy : 1.f - wy) : 0.f;
            int cx = min(max(ix, 0), WW - 1);
            int cy = min(max(iy, 0), HH - 1);
            s_w[it][c] = wgt;
            s_idx[it][c] = cy * WW + cx;
        }
    }
    __syncthreads();

    const int h = tid >> 5, lane = tid & 31;
    const __half* vb = g_vh + (long)b * HWSZ * DD + h * HDIM + lane;
    float acc = 0.f;
    const int base = h * 40;
#pragma unroll 4
    for (int i = 0; i < 40; i++) {
#pragma unroll
        for (int c = 0; c < 4; c++) {
            float w = s_w[base + i][c];
            int idx = s_idx[base + i][c];
            acc = fmaf(w, __half2float(vb[(long)idx * DD]), acc);
        }
    }
    g_s[(long)bn * DD + h * HDIM + lane] = acc;
}

// ---------------- launch ----------------
extern "C" void kernel_launch(void* const* d_in, const int* in_sizes, int n_in,
                              void* d_out, int out_size)
{
    const float* query = (const float*)d_in[0];
    const float* ctrl  = (const float*)d_in[1];
    const float* bev   = (const float*)d_in[2];
    const float* pc    = (const float*)d_in[4];
    const float* Wq    = (const float*)d_in[5];
    const float* bq    = (const float*)d_in[6];
    const float* Wv    = (const float*)d_in[7];
    const float* bv    = (const float*)d_in[8];
    const float* Woff  = (const float*)d_in[9];
    const float* boff  = (const float*)d_in[10];
    const float* Wattn = (const float*)d_in[11];
    const float* battn = (const float*)d_in[12];
    const float* Wmo   = (const float*)d_in[13];
    const float* bmo   = (const float*)d_in[14];
    const float* Wo    = (const float*)d_in[15];
    const float* bo    = (const float*)d_in[16];
    float* out = (float*)d_out;

    float *pq, *ps, *pt;
    cudaGetSymbolAddress((void**)&pq, g_q);
    cudaGetSymbolAddress((void**)&ps, g_s);
    cudaGetSymbolAddress((void**)&pt, g_t);

    cudaFuncSetAttribute(gemm_v, cudaFuncAttributeMaxDynamicSharedMemorySize, V_SMEM);
    cudaFuncSetAttribute(gemm_small<false>, cudaFuncAttributeMaxDynamicSharedMemorySize, S_SMEM);
    cudaFuncSetAttribute(gemm_small<true>, cudaFuncAttributeMaxDynamicSharedMemorySize, S_SMEM);

    const int Mq = BB * NQ;                     // 3600
    const dim3 sg_grid(2, (Mq + 63) / 64);      // 2 x 57

    // q = query @ Wq + bq
    gemm_small<false><<<sg_grid, 256, S_SMEM>>>(query, Wq, bq, nullptr, pq, Mq);

    // offsets + attention weights
    offattn_kernel<<<Mq, 128>>>(Woff, boff, Wattn, battn);

    // Wv -> WvT fp16
    conv_wv<<<DD, 256>>>(Wv);

    // v = bev^T @ Wv + bv  (fp16 output)
    gemm_v<<<dim3(HWSZ / 64, BB), 256, V_SMEM>>>(bev, bv);

    // bezier + bilinear sampling + attention-weighted sum
    sample_kernel<<<BB * NQ, 256>>>(ctrl, pc);

    // t = s @ Wmo + bmo + q
    gemm_small<true><<<sg_grid, 256, S_SMEM>>>(ps, Wmo, bmo, pq, pt, Mq);

    // out = t @ Wo + bo
    gemm_small<false><<<sg_grid, 256, S_SMEM>>>(pt, Wo, bo, nullptr, out, Mq);
}